// round 2
// baseline (speedup 1.0000x reference)
#include <cuda_runtime.h>
#include <math.h>

#define B_  32
#define T_  512
#define D_  1024
#define H_  16
#define HD_ 64
#define M_  (B_ * T_)      // 16384 rows
#define N3  (3 * D_)       // 3072 fused kqv columns

// ---------------- device scratch (no allocations allowed) ----------------
__device__ float g_h[M_ * D_];                 // 64 MB
__device__ float g_kqv[M_ * N3];               // 192 MB: [bt, {k|q|v} h e]
__device__ float g_attn[M_ * D_];              // 64 MB: [bt, h*64+e]
__device__ float g_wkqv[D_ * N3];              // 12 MB repacked weights
__device__ float g_bkqv[N3];

// ---------------- weight repack: [H,D,HD]x3 -> [D, 3*1024] ----------------
__global__ void repack_kernel(const float* __restrict__ Wk, const float* __restrict__ Wq,
                              const float* __restrict__ Wv, const float* __restrict__ bk,
                              const float* __restrict__ bq, const float* __restrict__ bv) {
    int idx = blockIdx.x * blockDim.x + threadIdx.x;
    const int per = H_ * D_ * HD_;           // 1,048,576
    if (idx < 3 * per) {
        int w  = idx / per;
        int r  = idx % per;
        int h  = r / (D_ * HD_);
        int r2 = r % (D_ * HD_);
        int d  = r2 / HD_;
        int e  = r2 % HD_;
        const float* src = (w == 0) ? Wk : ((w == 1) ? Wq : Wv);
        g_wkqv[d * N3 + w * D_ + h * HD_ + e] = src[h * D_ * HD_ + d * HD_ + e];
    }
    if (idx < N3) {
        int w = idx / D_;
        int c = idx % D_;
        const float* bsrc = (w == 0) ? bk : ((w == 1) ? bq : bv);
        g_bkqv[idx] = bsrc[c];   // bk is [H,HD] contiguous == column order h*64+e
    }
}

// ---------------- fp32 SGEMM + bias: C[M,N] = A[M,K] @ B[K,N] + bias ----------------
// 128x128 block tile, BK=8, 8x8 per-thread microtile, 256 threads.
// All dims here are multiples of the tile sizes (no bounds checks).
__global__ void __launch_bounds__(256, 2)
sgemm_bias(int M, int N, int K,
           const float* __restrict__ A, const float* __restrict__ Bm,
           const float* __restrict__ bias, float* __restrict__ C) {
    constexpr int BM = 128, BN = 128, BK = 8, TM = 8, TN = 8;
    __shared__ float As[BK][BM];   // A stored transposed
    __shared__ float Bs[BK][BN];

    const int tid = threadIdx.x;
    const int bm = blockIdx.y, bn = blockIdx.x;
    const int tRow = tid / (BN / TN);   // 0..15
    const int tCol = tid % (BN / TN);   // 0..15

    // load index mapping
    const int aRow = tid / 2;           // 0..127 (128 rows, 2 float4 per 8-wide row)
    const int aCol = tid % 2;           // 0..1
    const int bRow = tid / 32;          // 0..7
    const int bCol = tid % 32;          // 0..31

    const float* Ab = A + (size_t)bm * BM * K;
    const float* Bb = Bm + bn * BN;

    float acc[TM][TN] = {};

    for (int k0 = 0; k0 < K; k0 += BK) {
        float4 a4 = *(const float4*)(Ab + (size_t)aRow * K + k0 + aCol * 4);
        As[aCol * 4 + 0][aRow] = a4.x;
        As[aCol * 4 + 1][aRow] = a4.y;
        As[aCol * 4 + 2][aRow] = a4.z;
        As[aCol * 4 + 3][aRow] = a4.w;
        *(float4*)(&Bs[bRow][bCol * 4]) =
            *(const float4*)(Bb + (size_t)(k0 + bRow) * N + bCol * 4);
        __syncthreads();

        #pragma unroll
        for (int k = 0; k < BK; k++) {
            float rM[TM], rN[TN];
            #pragma unroll
            for (int i = 0; i < TM; i++) rM[i] = As[k][tRow * TM + i];
            #pragma unroll
            for (int j = 0; j < TN; j++) rN[j] = Bs[k][tCol * TN + j];
            #pragma unroll
            for (int i = 0; i < TM; i++)
                #pragma unroll
                for (int j = 0; j < TN; j++)
                    acc[i][j] += rM[i] * rN[j];
        }
        __syncthreads();
    }

    #pragma unroll
    for (int i = 0; i < TM; i++) {
        int row = bm * BM + tRow * TM + i;
        #pragma unroll
        for (int j = 0; j < TN; j += 4) {
            int col = bn * BN + tCol * TN + j;
            float4 o;
            o.x = acc[i][j + 0] + bias[col + 0];
            o.y = acc[i][j + 1] + bias[col + 1];
            o.z = acc[i][j + 2] + bias[col + 2];
            o.w = acc[i][j + 3] + bias[col + 3];
            *(float4*)(C + (size_t)row * N + col) = o;
        }
    }
}

// ---------------- fused causal attention (flash-style) ----------------
// Reference semantics: score[t][s] = k_t . q_s, mask s<=t, softmax over s,
// out[t] = sum_s p[t][s] * v[s].  One block = one (b, h, 64-row t-chunk).
// Each of 64 threads owns one row t: k-row + output accumulator in registers.
__global__ void __launch_bounds__(64)
attn_kernel(const float* __restrict__ kqv, float* __restrict__ out) {
    const int tchunk = blockIdx.x;   // 0..7
    const int h      = blockIdx.y;   // 0..15
    const int b      = blockIdx.z;   // 0..31
    const int tid    = threadIdx.x;  // 0..63
    const int t      = tchunk * 64 + tid;

    __shared__ float qs[64][64];
    __shared__ float vs[64][64];
    __shared__ float sc[64][65];     // +1 pad: conflict-free per-row access

    // this thread's k row (the "query" of the swapped attention)
    float kr[64];
    const float* krow = kqv + (size_t)(b * T_ + t) * N3 + h * HD_;
    #pragma unroll
    for (int d = 0; d < 64; d += 4) {
        float4 v4 = *(const float4*)(krow + d);
        kr[d] = v4.x; kr[d + 1] = v4.y; kr[d + 2] = v4.z; kr[d + 3] = v4.w;
    }

    float m = -INFINITY, l = 0.f;
    float acc[64];
    #pragma unroll
    for (int d = 0; d < 64; d++) acc[d] = 0.f;

    for (int c = 0; c <= tchunk; c++) {
        // cooperative load of q chunk and v chunk: 64x64 floats each
        #pragma unroll
        for (int it = 0; it < 16; it++) {
            int idx = it * 64 + tid;        // 0..1023 float4 slots
            int row = idx >> 4;             // 0..63
            int f4  = idx & 15;             // 0..15
            const float* qrow = kqv + (size_t)(b * T_ + c * 64 + row) * N3 + D_ + h * HD_;
            ((float4*)qs)[row * 16 + f4] = *(const float4*)(qrow + f4 * 4);
            ((float4*)vs)[row * 16 + f4] = *(const float4*)(qrow + D_ + f4 * 4);
        }
        __syncthreads();

        // pass 1: scores for this chunk, track chunk max
        const bool last = (c == tchunk);
        float cmax = -INFINITY;
        for (int j = 0; j < 64; j++) {
            float s;
            if (last && j > tid) {
                s = -INFINITY;               // causal mask: s_global > t
            } else {
                s = 0.f;
                const float4* q4 = (const float4*)(&qs[j][0]);
                #pragma unroll
                for (int d4 = 0; d4 < 16; d4++) {
                    float4 qq = q4[d4];      // broadcast across warp
                    s += kr[4 * d4 + 0] * qq.x + kr[4 * d4 + 1] * qq.y
                       + kr[4 * d4 + 2] * qq.z + kr[4 * d4 + 3] * qq.w;
                }
            }
            sc[tid][j] = s;
            cmax = fmaxf(cmax, s);
        }

        float mnew  = fmaxf(m, cmax);
        float alpha = __expf(m - mnew);      // 0 when m == -inf
        l *= alpha;
        #pragma unroll
        for (int d = 0; d < 64; d++) acc[d] *= alpha;
        m = mnew;

        // pass 2: p = exp(s - m), rank-1 update into accumulator
        for (int j = 0; j < 64; j++) {
            float p = __expf(sc[tid][j] - m);   // 0 for masked (-inf) entries
            l += p;
            const float4* v4 = (const float4*)(&vs[j][0]);
            #pragma unroll
            for (int d4 = 0; d4 < 16; d4++) {
                float4 vv = v4[d4];
                acc[4 * d4 + 0] += p * vv.x;
                acc[4 * d4 + 1] += p * vv.y;
                acc[4 * d4 + 2] += p * vv.z;
                acc[4 * d4 + 3] += p * vv.w;
            }
        }
        __syncthreads();
    }

    const float inv = 1.f / l;
    float* orow = out + (size_t)(b * T_ + t) * D_ + h * HD_;
    #pragma unroll
    for (int d = 0; d < 64; d += 4) {
        float4 o;
        o.x = acc[d + 0] * inv; o.y = acc[d + 1] * inv;
        o.z = acc[d + 2] * inv; o.w = acc[d + 3] * inv;
        *(float4*)(orow + d) = o;
    }
}

// ---------------- launch ----------------
extern "C" void kernel_launch(void* const* d_in, const int* in_sizes, int n_in,
                              void* d_out, int out_size) {
    const float* x  = (const float*)d_in[0];
    const float* Wi = (const float*)d_in[1];
    const float* bi = (const float*)d_in[2];
    const float* Wk = (const float*)d_in[3];
    const float* bk = (const float*)d_in[4];
    const float* Wq = (const float*)d_in[5];
    const float* bq = (const float*)d_in[6];
    const float* Wv = (const float*)d_in[7];
    const float* bv = (const float*)d_in[8];
    const float* Wo = (const float*)d_in[9];
    const float* bo = (const float*)d_in[10];
    float* out = (float*)d_out;

    float *p_h, *p_kqv, *p_attn, *p_wkqv, *p_bkqv;
    cudaGetSymbolAddress((void**)&p_h,    g_h);
    cudaGetSymbolAddress((void**)&p_kqv,  g_kqv);
    cudaGetSymbolAddress((void**)&p_attn, g_attn);
    cudaGetSymbolAddress((void**)&p_wkqv, g_wkqv);
    cudaGetSymbolAddress((void**)&p_bkqv, g_bkqv);

    // 1) repack the per-head weights into one [D, 3072] matrix
    repack_kernel<<<(3 * H_ * D_ * HD_ + 255) / 256, 256>>>(Wk, Wq, Wv, bk, bq, bv);

    // 2) h = x @ Wi + bi                                  [16384 x 1024]
    {
        dim3 grid(D_ / 128, M_ / 128);
        sgemm_bias<<<grid, 256>>>(M_, D_, D_, x, Wi, bi, p_h);
    }
    // 3) kqv = h @ Wkqv + bkqv                            [16384 x 3072]
    {
        dim3 grid(N3 / 128, M_ / 128);
        sgemm_bias<<<grid, 256>>>(M_, N3, D_, p_h, p_wkqv, p_bkqv, p_kqv);
    }
    // 4) fused causal attention -> attn_out               [16384 x 1024]
    {
        dim3 grid(T_ / 64, H_, B_);
        attn_kernel<<<grid, 64>>>(p_kqv, p_attn);
    }
    // 5) out = attn_out @ Wo + bo                         [16384 x 1024]
    {
        dim3 grid(D_ / 128, M_ / 128);
        sgemm_bias<<<grid, 256>>>(M_, D_, D_, p_attn, Wo, bo, out);
    }
}

// round 4
// speedup vs baseline: 1.7356x; 1.7356x over previous
#include <cuda_runtime.h>
#include <cuda_bf16.h>
#include <math.h>
#include <stdint.h>

#define B_  32
#define T_  512
#define D_  1024
#define H_  16
#define HD_ 64
#define M_  (B_ * T_)      // 16384 rows
#define N3  (3 * D_)       // 3072 fused kqv columns

// ---------------- device scratch (no allocations allowed) ----------------
__device__ float g_h[M_ * D_];                 // 64 MB
__device__ float g_kqv[M_ * N3];               // 192 MB: [bt, {k|q|v} h e]
__device__ float g_attn[M_ * D_];              // 64 MB
__device__ float g_wkqv[D_ * N3];              // 12 MB repacked weights
__device__ float g_bkqv[N3];

// ---------------- weight repack: [H,D,HD]x3 -> [D, 3*1024] ----------------
__global__ void repack_kernel(const float* __restrict__ Wk, const float* __restrict__ Wq,
                              const float* __restrict__ Wv, const float* __restrict__ bk,
                              const float* __restrict__ bq, const float* __restrict__ bv) {
    int idx = blockIdx.x * blockDim.x + threadIdx.x;
    const int per = H_ * D_ * HD_;           // 1,048,576
    if (idx < 3 * per) {
        int w  = idx / per;
        int r  = idx % per;
        int h  = r / (D_ * HD_);
        int r2 = r % (D_ * HD_);
        int d  = r2 / HD_;
        int e  = r2 % HD_;
        const float* src = (w == 0) ? Wk : ((w == 1) ? Wq : Wv);
        g_wkqv[d * N3 + w * D_ + h * HD_ + e] = src[h * D_ * HD_ + d * HD_ + e];
    }
    if (idx < N3) {
        int w = idx / D_;
        int c = idx % D_;
        const float* bsrc = (w == 0) ? bk : ((w == 1) ? bq : bv);
        g_bkqv[idx] = bsrc[c];
    }
}

// =======================================================================
// bf16x3 split-precision tensor-core GEMM
// C[M,N] = A[M,K] @ B[K,N] + bias, all fp32 in global memory.
// A,B split on the fly into hi/lo bf16; C = Ah*Bh + Al*Bh + Ah*Bl in fp32 acc.
// Block tile 128x128x32, 256 threads (8 warps), warp tile 64x32,
// m16n8k16 mma fragments, double-buffered smem (72KB dynamic).
// =======================================================================
#define BM 128
#define BN 128
#define BKK 32
#define A_STRIDE 80               /* bytes per smem A row: 40 bf16, %16==0, conflict-free */
#define A_MAT (128 * A_STRIDE)    /* 10240 */
#define B_MAT (32 * 256)          /* 8192  */
#define BUFSZ (2 * A_MAT + 2 * B_MAT)  /* 36864 */
#define GEMM_SMEM (2 * BUFSZ)          /* 73728 */

__device__ __forceinline__ void cvt8(const float* f, uint4& hi, uint4& lo) {
    unsigned int h[4], l[4];
    #pragma unroll
    for (int i = 0; i < 4; i++) {
        __nv_bfloat16 b0 = __float2bfloat16_rn(f[2 * i]);
        __nv_bfloat16 b1 = __float2bfloat16_rn(f[2 * i + 1]);
        __nv_bfloat16 c0 = __float2bfloat16_rn(f[2 * i]     - __bfloat162float(b0));
        __nv_bfloat16 c1 = __float2bfloat16_rn(f[2 * i + 1] - __bfloat162float(b1));
        h[i] = (unsigned)__bfloat16_as_ushort(b0) | ((unsigned)__bfloat16_as_ushort(b1) << 16);
        l[i] = (unsigned)__bfloat16_as_ushort(c0) | ((unsigned)__bfloat16_as_ushort(c1) << 16);
    }
    hi = make_uint4(h[0], h[1], h[2], h[3]);
    lo = make_uint4(l[0], l[1], l[2], l[3]);
}

// ldmatrix x4 (A, row-major m16k16): lane -> (matrix = lane/8) row segment
__device__ __forceinline__ void ldmA(uint32_t* r, uint32_t base, int m0, int kk, int lane) {
    int mrow = m0 + (lane & 7) + ((lane >> 3) & 1) * 8;
    int kcol = kk + (lane >> 4) * 8;
    uint32_t addr = base + mrow * A_STRIDE + kcol * 2;
    asm volatile("ldmatrix.sync.aligned.m8n8.x4.shared.b16 {%0,%1,%2,%3}, [%4];"
                 : "=r"(r[0]), "=r"(r[1]), "=r"(r[2]), "=r"(r[3]) : "r"(addr));
}

// ldmatrix x4 trans (B, row-major [BK][BN], XOR-swizzled 16B chunks)
__device__ __forceinline__ void ldmB(uint32_t* b0, uint32_t* b1, uint32_t base,
                                     int kk, int nb, int lane) {
    int krow  = kk + (lane & 7) + ((lane >> 3) & 1) * 8;
    int nc    = nb + (lane >> 4) * 8;
    int chunk = (nc >> 3) ^ (krow & 7);
    uint32_t addr = base + krow * 256 + chunk * 16;
    uint32_t r0, r1, r2, r3;
    asm volatile("ldmatrix.sync.aligned.m8n8.x4.trans.shared.b16 {%0,%1,%2,%3}, [%4];"
                 : "=r"(r0), "=r"(r1), "=r"(r2), "=r"(r3) : "r"(addr));
    b0[0] = r0; b0[1] = r1; b1[0] = r2; b1[1] = r3;
}

__device__ __forceinline__ void mma_bf16(float* d, const uint32_t* a, const uint32_t* b) {
    asm volatile("mma.sync.aligned.m16n8k16.row.col.f32.bf16.bf16.f32 "
                 "{%0,%1,%2,%3}, {%4,%5,%6,%7}, {%8,%9}, {%0,%1,%2,%3};"
                 : "+f"(d[0]), "+f"(d[1]), "+f"(d[2]), "+f"(d[3])
                 : "r"(a[0]), "r"(a[1]), "r"(a[2]), "r"(a[3]), "r"(b[0]), "r"(b[1]));
}

__global__ void __launch_bounds__(256, 1)
gemm_bf16x3(int M, int N, int K,
            const float* __restrict__ A, const float* __restrict__ Bm,
            const float* __restrict__ bias, float* __restrict__ C) {
    extern __shared__ char sm[];
    const int tid = threadIdx.x, lane = tid & 31, wid = tid >> 5;
    const int bm = blockIdx.y, bn = blockIdx.x;
    const int warp_m = wid >> 2, warp_n = wid & 3;

    uint32_t sbase = (uint32_t)__cvta_generic_to_shared(sm);

    const int aRow = tid >> 1, aC = (tid & 1) * 16;   // A: 128 rows x 32 cols, 16 floats/thread
    const int bRow = tid >> 3, bC = (tid & 7) * 16;   // B: 32 rows x 128 cols, 16 floats/thread

    const float* Ag = A + (size_t)(bm * BM + aRow) * K + aC;
    const float* Bg = Bm + (size_t)bRow * N + (size_t)bn * BN + bC;

    float acc[4][4][4] = {};
    float4 ra[4], rb[4];
    const int NT = K / BKK;

    auto store_stage = [&](int buf) {
        char* base = sm + buf * BUFSZ;
        {   // A tile -> hi/lo
            float tmp[16];
            #pragma unroll
            for (int i = 0; i < 4; i++) {
                tmp[4*i] = ra[i].x; tmp[4*i+1] = ra[i].y; tmp[4*i+2] = ra[i].z; tmp[4*i+3] = ra[i].w;
            }
            uint4 h0, l0, h1, l1;
            cvt8(tmp, h0, l0); cvt8(tmp + 8, h1, l1);
            int off = aRow * A_STRIDE + aC * 2;
            *(uint4*)(base + off)              = h0;
            *(uint4*)(base + off + 16)         = h1;
            *(uint4*)(base + A_MAT + off)      = l0;
            *(uint4*)(base + A_MAT + off + 16) = l1;
        }
        {   // B tile -> hi/lo, XOR swizzle by 16B chunk
            float tmp[16];
            #pragma unroll
            for (int i = 0; i < 4; i++) {
                tmp[4*i] = rb[i].x; tmp[4*i+1] = rb[i].y; tmp[4*i+2] = rb[i].z; tmp[4*i+3] = rb[i].w;
            }
            uint4 h0, l0, h1, l1;
            cvt8(tmp, h0, l0); cvt8(tmp + 8, h1, l1);
            int c0 = ((bC >> 3) + 0) ^ (bRow & 7);
            int c1 = ((bC >> 3) + 1) ^ (bRow & 7);
            char* bb = base + 2 * A_MAT;
            *(uint4*)(bb + bRow * 256 + c0 * 16)         = h0;
            *(uint4*)(bb + bRow * 256 + c1 * 16)         = h1;
            *(uint4*)(bb + B_MAT + bRow * 256 + c0 * 16) = l0;
            *(uint4*)(bb + B_MAT + bRow * 256 + c1 * 16) = l1;
        }
    };

    // prologue: stage 0
    #pragma unroll
    for (int i = 0; i < 4; i++) ra[i] = *(const float4*)(Ag + i * 4);
    #pragma unroll
    for (int i = 0; i < 4; i++) rb[i] = *(const float4*)(Bg + i * 4);
    store_stage(0);
    __syncthreads();

    for (int kt = 0; kt < NT; kt++) {
        int cur = kt & 1;
        if (kt + 1 < NT) {   // prefetch next tile into registers
            const float* Ag2 = Ag + (kt + 1) * BKK;
            const float* Bg2 = Bg + (size_t)(kt + 1) * BKK * N;
            #pragma unroll
            for (int i = 0; i < 4; i++) ra[i] = *(const float4*)(Ag2 + i * 4);
            #pragma unroll
            for (int i = 0; i < 4; i++) rb[i] = *(const float4*)(Bg2 + i * 4);
        }
        uint32_t Ah = sbase + cur * BUFSZ;
        uint32_t Al = Ah + A_MAT;
        uint32_t Bh = Ah + 2 * A_MAT;
        uint32_t Bl = Bh + B_MAT;

        #pragma unroll
        for (int kk = 0; kk < BKK; kk += 16) {
            uint32_t bh[4][2], bl[4][2];
            ldmB(bh[0], bh[1], Bh, kk, warp_n * 32,      lane);
            ldmB(bh[2], bh[3], Bh, kk, warp_n * 32 + 16, lane);
            ldmB(bl[0], bl[1], Bl, kk, warp_n * 32,      lane);
            ldmB(bl[2], bl[3], Bl, kk, warp_n * 32 + 16, lane);
            #pragma unroll
            for (int mt = 0; mt < 4; mt++) {
                uint32_t ah[4], al[4];
                ldmA(ah, Ah, warp_m * 64 + mt * 16, kk, lane);
                ldmA(al, Al, warp_m * 64 + mt * 16, kk, lane);
                #pragma unroll
                for (int nt = 0; nt < 4; nt++) mma_bf16(acc[mt][nt], ah, bh[nt]);
                #pragma unroll
                for (int nt = 0; nt < 4; nt++) mma_bf16(acc[mt][nt], al, bh[nt]);
                #pragma unroll
                for (int nt = 0; nt < 4; nt++) mma_bf16(acc[mt][nt], ah, bl[nt]);
            }
        }
        if (kt + 1 < NT) store_stage(cur ^ 1);
        __syncthreads();
    }

    // epilogue: fragment layout (row = lane/4 [+8], col = (lane%4)*2 [+1])
    #pragma unroll
    for (int mt = 0; mt < 4; mt++) {
        int r0 = bm * BM + warp_m * 64 + mt * 16 + (lane >> 2);
        #pragma unroll
        for (int nt = 0; nt < 4; nt++) {
            int c = bn * BN + warp_n * 32 + nt * 8 + (lane & 3) * 2;
            float2 b2 = *(const float2*)(bias + c);
            float2 o0 = make_float2(acc[mt][nt][0] + b2.x, acc[mt][nt][1] + b2.y);
            float2 o1 = make_float2(acc[mt][nt][2] + b2.x, acc[mt][nt][3] + b2.y);
            *(float2*)(C + (size_t)r0 * N + c)       = o0;
            *(float2*)(C + (size_t)(r0 + 8) * N + c) = o1;
        }
    }
}

// ---------------- fused causal attention (flash-style, fp32) ----------------
__global__ void __launch_bounds__(64)
attn_kernel(const float* __restrict__ kqv, float* __restrict__ out) {
    const int tchunk = blockIdx.x;
    const int h      = blockIdx.y;
    const int b      = blockIdx.z;
    const int tid    = threadIdx.x;
    const int t      = tchunk * 64 + tid;

    __shared__ float qs[64][64];
    __shared__ float vs[64][64];
    __shared__ float sc[64][65];

    float kr[64];
    const float* krow = kqv + (size_t)(b * T_ + t) * N3 + h * HD_;
    #pragma unroll
    for (int d = 0; d < 64; d += 4) {
        float4 v4 = *(const float4*)(krow + d);
        kr[d] = v4.x; kr[d + 1] = v4.y; kr[d + 2] = v4.z; kr[d + 3] = v4.w;
    }

    float m = -INFINITY, l = 0.f;
    float acc[64];
    #pragma unroll
    for (int d = 0; d < 64; d++) acc[d] = 0.f;

    for (int c = 0; c <= tchunk; c++) {
        #pragma unroll
        for (int it = 0; it < 16; it++) {
            int idx = it * 64 + tid;
            int row = idx >> 4;
            int f4  = idx & 15;
            const float* qrow = kqv + (size_t)(b * T_ + c * 64 + row) * N3 + D_ + h * HD_;
            ((float4*)qs)[row * 16 + f4] = *(const float4*)(qrow + f4 * 4);
            ((float4*)vs)[row * 16 + f4] = *(const float4*)(qrow + D_ + f4 * 4);
        }
        __syncthreads();

        const bool last = (c == tchunk);
        float cmax = -INFINITY;
        for (int j = 0; j < 64; j++) {
            float s;
            if (last && j > tid) {
                s = -INFINITY;
            } else {
                s = 0.f;
                const float4* q4 = (const float4*)(&qs[j][0]);
                #pragma unroll
                for (int d4 = 0; d4 < 16; d4++) {
                    float4 qq = q4[d4];
                    s += kr[4 * d4 + 0] * qq.x + kr[4 * d4 + 1] * qq.y
                       + kr[4 * d4 + 2] * qq.z + kr[4 * d4 + 3] * qq.w;
                }
            }
            sc[tid][j] = s;
            cmax = fmaxf(cmax, s);
        }

        float mnew  = fmaxf(m, cmax);
        float alpha = __expf(m - mnew);
        l *= alpha;
        #pragma unroll
        for (int d = 0; d < 64; d++) acc[d] *= alpha;
        m = mnew;

        for (int j = 0; j < 64; j++) {
            float p = __expf(sc[tid][j] - m);
            l += p;
            const float4* v4 = (const float4*)(&vs[j][0]);
            #pragma unroll
            for (int d4 = 0; d4 < 16; d4++) {
                float4 vv = v4[d4];
                acc[4 * d4 + 0] += p * vv.x;
                acc[4 * d4 + 1] += p * vv.y;
                acc[4 * d4 + 2] += p * vv.z;
                acc[4 * d4 + 3] += p * vv.w;
            }
        }
        __syncthreads();
    }

    const float inv = 1.f / l;
    float* orow = out + (size_t)(b * T_ + t) * D_ + h * HD_;
    #pragma unroll
    for (int d = 0; d < 64; d += 4) {
        float4 o;
        o.x = acc[d + 0] * inv; o.y = acc[d + 1] * inv;
        o.z = acc[d + 2] * inv; o.w = acc[d + 3] * inv;
        *(float4*)(orow + d) = o;
    }
}

// ---------------- launch ----------------
extern "C" void kernel_launch(void* const* d_in, const int* in_sizes, int n_in,
                              void* d_out, int out_size) {
    const float* x  = (const float*)d_in[0];
    const float* Wi = (const float*)d_in[1];
    const float* bi = (const float*)d_in[2];
    const float* Wk = (const float*)d_in[3];
    const float* bk = (const float*)d_in[4];
    const float* Wq = (const float*)d_in[5];
    const float* bq = (const float*)d_in[6];
    const float* Wv = (const float*)d_in[7];
    const float* bv = (const float*)d_in[8];
    const float* Wo = (const float*)d_in[9];
    const float* bo = (const float*)d_in[10];
    float* out = (float*)d_out;

    float *p_h, *p_kqv, *p_attn, *p_wkqv, *p_bkqv;
    cudaGetSymbolAddress((void**)&p_h,    g_h);
    cudaGetSymbolAddress((void**)&p_kqv,  g_kqv);
    cudaGetSymbolAddress((void**)&p_attn, g_attn);
    cudaGetSymbolAddress((void**)&p_wkqv, g_wkqv);
    cudaGetSymbolAddress((void**)&p_bkqv, g_bkqv);

    static bool attr_set = false;
    if (!attr_set) {
        cudaFuncSetAttribute(gemm_bf16x3, cudaFuncAttributeMaxDynamicSharedMemorySize, GEMM_SMEM);
        attr_set = true;
    }

    // 1) repack weights
    repack_kernel<<<(3 * H_ * D_ * HD_ + 255) / 256, 256>>>(Wk, Wq, Wv, bk, bq, bv);

    // 2) h = x @ Wi + bi
    {
        dim3 grid(D_ / BN, M_ / BM);
        gemm_bf16x3<<<grid, 256, GEMM_SMEM>>>(M_, D_, D_, x, Wi, bi, p_h);
    }
    // 3) kqv = h @ Wkqv + bkqv
    {
        dim3 grid(N3 / BN, M_ / BM);
        gemm_bf16x3<<<grid, 256, GEMM_SMEM>>>(M_, N3, D_, p_h, p_wkqv, p_bkqv, p_kqv);
    }
    // 4) fused causal attention
    {
        dim3 grid(T_ / 64, H_, B_);
        attn_kernel<<<grid, 64>>>(p_kqv, p_attn);
    }
    // 5) out = attn @ Wo + bo
    {
        dim3 grid(D_ / BN, M_ / BM);
        gemm_bf16x3<<<grid, 256, GEMM_SMEM>>>(M_, D_, D_, p_attn, Wo, bo, out);
    }
}

// round 5
// speedup vs baseline: 2.1749x; 1.2531x over previous
#include <cuda_runtime.h>
#include <cuda_bf16.h>
#include <math.h>
#include <stdint.h>

#define B_  32
#define T_  512
#define D_  1024
#define H_  16
#define HD_ 64
#define M_  (B_ * T_)      // 16384 rows
#define N3  (3 * D_)       // 3072 fused kqv columns

#define NEG_INF __int_as_float(0xff800000)

// ---------------- device scratch (no allocations allowed) ----------------
__device__ float g_h[M_ * D_];                 // 64 MB
__device__ float g_kqv[M_ * N3];               // 192 MB: [bt, {k|q|v} h e]
__device__ float g_attn[M_ * D_];              // 64 MB
__device__ float g_wkqv[D_ * N3];              // 12 MB repacked weights
__device__ float g_bkqv[N3];

// ---------------- weight repack ----------------
__global__ void repack_kernel(const float* __restrict__ Wk, const float* __restrict__ Wq,
                              const float* __restrict__ Wv, const float* __restrict__ bk,
                              const float* __restrict__ bq, const float* __restrict__ bv) {
    int idx = blockIdx.x * blockDim.x + threadIdx.x;
    const int per = H_ * D_ * HD_;
    if (idx < 3 * per) {
        int w  = idx / per;
        int r  = idx % per;
        int h  = r / (D_ * HD_);
        int r2 = r % (D_ * HD_);
        int d  = r2 / HD_;
        int e  = r2 % HD_;
        const float* src = (w == 0) ? Wk : ((w == 1) ? Wq : Wv);
        g_wkqv[d * N3 + w * D_ + h * HD_ + e] = src[h * D_ * HD_ + d * HD_ + e];
    }
    if (idx < N3) {
        int w = idx / D_;
        int c = idx % D_;
        const float* bsrc = (w == 0) ? bk : ((w == 1) ? bq : bv);
        g_bkqv[idx] = bsrc[c];
    }
}

// ---------------- shared helpers ----------------
__device__ __forceinline__ void cvt8(const float* f, uint4& hi, uint4& lo) {
    unsigned int h[4], l[4];
    #pragma unroll
    for (int i = 0; i < 4; i++) {
        __nv_bfloat16 b0 = __float2bfloat16_rn(f[2 * i]);
        __nv_bfloat16 b1 = __float2bfloat16_rn(f[2 * i + 1]);
        __nv_bfloat16 c0 = __float2bfloat16_rn(f[2 * i]     - __bfloat162float(b0));
        __nv_bfloat16 c1 = __float2bfloat16_rn(f[2 * i + 1] - __bfloat162float(b1));
        h[i] = (unsigned)__bfloat16_as_ushort(b0) | ((unsigned)__bfloat16_as_ushort(b1) << 16);
        l[i] = (unsigned)__bfloat16_as_ushort(c0) | ((unsigned)__bfloat16_as_ushort(c1) << 16);
    }
    hi = make_uint4(h[0], h[1], h[2], h[3]);
    lo = make_uint4(l[0], l[1], l[2], l[3]);
}

__device__ __forceinline__ void mma_bf16(float* d, const uint32_t* a, const uint32_t* b) {
    asm volatile("mma.sync.aligned.m16n8k16.row.col.f32.bf16.bf16.f32 "
                 "{%0,%1,%2,%3}, {%4,%5,%6,%7}, {%8,%9}, {%0,%1,%2,%3};"
                 : "+f"(d[0]), "+f"(d[1]), "+f"(d[2]), "+f"(d[3])
                 : "r"(a[0]), "r"(a[1]), "r"(a[2]), "r"(a[3]), "r"(b[0]), "r"(b[1]));
}

// =======================================================================
// bf16x3 GEMM (unchanged from R4)
// =======================================================================
#define BM 128
#define BN 128
#define BKK 32
#define A_STRIDE 80
#define A_MAT (128 * A_STRIDE)
#define B_MAT (32 * 256)
#define BUFSZ (2 * A_MAT + 2 * B_MAT)
#define GEMM_SMEM (2 * BUFSZ)

__device__ __forceinline__ void ldmA(uint32_t* r, uint32_t base, int m0, int kk, int lane) {
    int mrow = m0 + (lane & 7) + ((lane >> 3) & 1) * 8;
    int kcol = kk + (lane >> 4) * 8;
    uint32_t addr = base + mrow * A_STRIDE + kcol * 2;
    asm volatile("ldmatrix.sync.aligned.m8n8.x4.shared.b16 {%0,%1,%2,%3}, [%4];"
                 : "=r"(r[0]), "=r"(r[1]), "=r"(r[2]), "=r"(r[3]) : "r"(addr));
}

__device__ __forceinline__ void ldmB(uint32_t* b0, uint32_t* b1, uint32_t base,
                                     int kk, int nb, int lane) {
    int krow  = kk + (lane & 7) + ((lane >> 3) & 1) * 8;
    int nc    = nb + (lane >> 4) * 8;
    int chunk = (nc >> 3) ^ (krow & 7);
    uint32_t addr = base + krow * 256 + chunk * 16;
    uint32_t r0, r1, r2, r3;
    asm volatile("ldmatrix.sync.aligned.m8n8.x4.trans.shared.b16 {%0,%1,%2,%3}, [%4];"
                 : "=r"(r0), "=r"(r1), "=r"(r2), "=r"(r3) : "r"(addr));
    b0[0] = r0; b0[1] = r1; b1[0] = r2; b1[1] = r3;
}

__global__ void __launch_bounds__(256, 1)
gemm_bf16x3(int M, int N, int K,
            const float* __restrict__ A, const float* __restrict__ Bm,
            const float* __restrict__ bias, float* __restrict__ C) {
    extern __shared__ char sm[];
    const int tid = threadIdx.x, lane = tid & 31, wid = tid >> 5;
    const int bm = blockIdx.y, bn = blockIdx.x;
    const int warp_m = wid >> 2, warp_n = wid & 3;

    uint32_t sbase = (uint32_t)__cvta_generic_to_shared(sm);

    const int aRow = tid >> 1, aC = (tid & 1) * 16;
    const int bRow = tid >> 3, bC = (tid & 7) * 16;

    const float* Ag = A + (size_t)(bm * BM + aRow) * K + aC;
    const float* Bg = Bm + (size_t)bRow * N + (size_t)bn * BN + bC;

    float acc[4][4][4] = {};
    float4 ra[4], rb[4];
    const int NT = K / BKK;

    auto store_stage = [&](int buf) {
        char* base = sm + buf * BUFSZ;
        {
            float tmp[16];
            #pragma unroll
            for (int i = 0; i < 4; i++) {
                tmp[4*i] = ra[i].x; tmp[4*i+1] = ra[i].y; tmp[4*i+2] = ra[i].z; tmp[4*i+3] = ra[i].w;
            }
            uint4 h0, l0, h1, l1;
            cvt8(tmp, h0, l0); cvt8(tmp + 8, h1, l1);
            int off = aRow * A_STRIDE + aC * 2;
            *(uint4*)(base + off)              = h0;
            *(uint4*)(base + off + 16)         = h1;
            *(uint4*)(base + A_MAT + off)      = l0;
            *(uint4*)(base + A_MAT + off + 16) = l1;
        }
        {
            float tmp[16];
            #pragma unroll
            for (int i = 0; i < 4; i++) {
                tmp[4*i] = rb[i].x; tmp[4*i+1] = rb[i].y; tmp[4*i+2] = rb[i].z; tmp[4*i+3] = rb[i].w;
            }
            uint4 h0, l0, h1, l1;
            cvt8(tmp, h0, l0); cvt8(tmp + 8, h1, l1);
            int c0 = ((bC >> 3) + 0) ^ (bRow & 7);
            int c1 = ((bC >> 3) + 1) ^ (bRow & 7);
            char* bb = base + 2 * A_MAT;
            *(uint4*)(bb + bRow * 256 + c0 * 16)         = h0;
            *(uint4*)(bb + bRow * 256 + c1 * 16)         = h1;
            *(uint4*)(bb + B_MAT + bRow * 256 + c0 * 16) = l0;
            *(uint4*)(bb + B_MAT + bRow * 256 + c1 * 16) = l1;
        }
    };

    #pragma unroll
    for (int i = 0; i < 4; i++) ra[i] = *(const float4*)(Ag + i * 4);
    #pragma unroll
    for (int i = 0; i < 4; i++) rb[i] = *(const float4*)(Bg + i * 4);
    store_stage(0);
    __syncthreads();

    for (int kt = 0; kt < NT; kt++) {
        int cur = kt & 1;
        if (kt + 1 < NT) {
            const float* Ag2 = Ag + (kt + 1) * BKK;
            const float* Bg2 = Bg + (size_t)(kt + 1) * BKK * N;
            #pragma unroll
            for (int i = 0; i < 4; i++) ra[i] = *(const float4*)(Ag2 + i * 4);
            #pragma unroll
            for (int i = 0; i < 4; i++) rb[i] = *(const float4*)(Bg2 + i * 4);
        }
        uint32_t Ah = sbase + cur * BUFSZ;
        uint32_t Al = Ah + A_MAT;
        uint32_t Bh = Ah + 2 * A_MAT;
        uint32_t Bl = Bh + B_MAT;

        #pragma unroll
        for (int kk = 0; kk < BKK; kk += 16) {
            uint32_t bh[4][2], bl[4][2];
            ldmB(bh[0], bh[1], Bh, kk, warp_n * 32,      lane);
            ldmB(bh[2], bh[3], Bh, kk, warp_n * 32 + 16, lane);
            ldmB(bl[0], bl[1], Bl, kk, warp_n * 32,      lane);
            ldmB(bl[2], bl[3], Bl, kk, warp_n * 32 + 16, lane);
            #pragma unroll
            for (int mt = 0; mt < 4; mt++) {
                uint32_t ah[4], al[4];
                ldmA(ah, Ah, warp_m * 64 + mt * 16, kk, lane);
                ldmA(al, Al, warp_m * 64 + mt * 16, kk, lane);
                #pragma unroll
                for (int nt = 0; nt < 4; nt++) mma_bf16(acc[mt][nt], ah, bh[nt]);
                #pragma unroll
                for (int nt = 0; nt < 4; nt++) mma_bf16(acc[mt][nt], al, bh[nt]);
                #pragma unroll
                for (int nt = 0; nt < 4; nt++) mma_bf16(acc[mt][nt], ah, bl[nt]);
            }
        }
        if (kt + 1 < NT) store_stage(cur ^ 1);
        __syncthreads();
    }

    #pragma unroll
    for (int mt = 0; mt < 4; mt++) {
        int r0 = bm * BM + warp_m * 64 + mt * 16 + (lane >> 2);
        #pragma unroll
        for (int nt = 0; nt < 4; nt++) {
            int c = bn * BN + warp_n * 32 + nt * 8 + (lane & 3) * 2;
            float2 b2 = *(const float2*)(bias + c);
            float2 o0 = make_float2(acc[mt][nt][0] + b2.x, acc[mt][nt][1] + b2.y);
            float2 o1 = make_float2(acc[mt][nt][2] + b2.x, acc[mt][nt][3] + b2.y);
            *(float2*)(C + (size_t)r0 * N + c)       = o0;
            *(float2*)(C + (size_t)(r0 + 8) * N + c) = o1;
        }
    }
}

// =======================================================================
// Tensor-core flash attention, bf16x3
// S[t][s] = k_t . q_s (causal s<=t), softmax over s, O[t] = sum_s P V.
// Block: 64 t-rows x (h,b); 4 warps, each owns 16 t-rows.
// Tiles 64x64 in smem as hi/lo bf16, 128B rows, 16B-chunk XOR swizzle.
// =======================================================================
#define ATT_MAT 8192   /* 64 rows * 128 bytes */

// A-operand fragments from [row][d] storage (non-trans), swizzled
__device__ __forceinline__ void ldmKA(uint32_t* r, uint32_t base, int m0, int kk, int lane) {
    int mrow  = m0 + (lane & 7) + ((lane >> 3) & 1) * 8;
    int chunk = ((kk >> 3) + (lane >> 4)) ^ (mrow & 7);
    uint32_t addr = base + mrow * 128 + chunk * 16;
    asm volatile("ldmatrix.sync.aligned.m8n8.x4.shared.b16 {%0,%1,%2,%3}, [%4];"
                 : "=r"(r[0]), "=r"(r[1]), "=r"(r[2]), "=r"(r[3]) : "r"(addr));
}

// B-operand fragments from row-major [n][k] storage (Q): non-trans ldmatrix.
// Covers 2 n-tiles (n0..n0+15) x k16 at kk. Out: t0 = ntile(n0), t1 = ntile(n0+8).
__device__ __forceinline__ void ldmQB(uint32_t* t0, uint32_t* t1, uint32_t base,
                                      int n0, int kk, int lane) {
    int g     = lane >> 3;
    int nrow  = n0 + (lane & 7) + (g >> 1) * 8;
    int chunk = ((kk >> 3) + (g & 1)) ^ (nrow & 7);
    uint32_t addr = base + nrow * 128 + chunk * 16;
    uint32_t r0, r1, r2, r3;
    asm volatile("ldmatrix.sync.aligned.m8n8.x4.shared.b16 {%0,%1,%2,%3}, [%4];"
                 : "=r"(r0), "=r"(r1), "=r"(r2), "=r"(r3) : "r"(addr));
    t0[0] = r0; t0[1] = r1; t1[0] = r2; t1[1] = r3;
}

// B-operand fragments from row-major [k][n] storage (V): trans ldmatrix.
__device__ __forceinline__ void ldmVB(uint32_t* t0, uint32_t* t1, uint32_t base,
                                      int kk, int nb, int lane) {
    int krow  = kk + (lane & 7) + ((lane >> 3) & 1) * 8;
    int nc    = nb + (lane >> 4) * 8;
    int chunk = (nc >> 3) ^ (krow & 7);
    uint32_t addr = base + krow * 128 + chunk * 16;
    uint32_t r0, r1, r2, r3;
    asm volatile("ldmatrix.sync.aligned.m8n8.x4.trans.shared.b16 {%0,%1,%2,%3}, [%4];"
                 : "=r"(r0), "=r"(r1), "=r"(r2), "=r"(r3) : "r"(addr));
    t0[0] = r0; t0[1] = r1; t1[0] = r2; t1[1] = r3;
}

// convert+store one 64x64 fp32 tile into hi/lo bf16 swizzled smem
__device__ __forceinline__ void cvstore_tile(const float* __restrict__ src,
                                             char* hi_base, char* lo_base,
                                             int row, int half) {
    #pragma unroll
    for (int c4 = 0; c4 < 4; c4++) {
        float tmp[8];
        float4 x0 = *(const float4*)(src + c4 * 8);
        float4 x1 = *(const float4*)(src + c4 * 8 + 4);
        tmp[0] = x0.x; tmp[1] = x0.y; tmp[2] = x0.z; tmp[3] = x0.w;
        tmp[4] = x1.x; tmp[5] = x1.y; tmp[6] = x1.z; tmp[7] = x1.w;
        uint4 h, l;
        cvt8(tmp, h, l);
        int chunk = (half * 4 + c4) ^ (row & 7);
        *(uint4*)(hi_base + row * 128 + chunk * 16) = h;
        *(uint4*)(lo_base + row * 128 + chunk * 16) = l;
    }
}

__global__ void __launch_bounds__(128)
attn_tc(const float* __restrict__ kqv, float* __restrict__ out) {
    __shared__ __align__(16) char smem[6 * ATT_MAT];   // kh kl qh ql vh vl
    char* p_kh = smem;
    char* p_kl = smem + ATT_MAT;
    char* p_qh = smem + 2 * ATT_MAT;
    char* p_ql = smem + 3 * ATT_MAT;
    char* p_vh = smem + 4 * ATT_MAT;
    char* p_vl = smem + 5 * ATT_MAT;

    const int tid = threadIdx.x, lane = tid & 31, w = tid >> 5;
    const int tchunk = blockIdx.x, h = blockIdx.y, b = blockIdx.z;
    const int tbase = tchunk * 64;

    uint32_t sb = (uint32_t)__cvta_generic_to_shared(smem);
    uint32_t s_kh = sb,                s_kl = sb + ATT_MAT;
    uint32_t s_qh = sb + 2 * ATT_MAT,  s_ql = sb + 3 * ATT_MAT;
    uint32_t s_vh = sb + 4 * ATT_MAT,  s_vl = sb + 5 * ATT_MAT;

    const int row  = tid >> 1;   // 0..63
    const int half = tid & 1;    // 0/1 -> 32-float half of the row

    // ---- K tile: load, convert, hold fragments in registers ----
    {
        const float* src = kqv + (size_t)(b * T_ + tbase + row) * N3 + h * HD_ + half * 32;
        cvstore_tile(src, p_kh, p_kl, row, half);
    }
    __syncthreads();

    uint32_t kh[4][4], kl[4][4];
    #pragma unroll
    for (int ks = 0; ks < 4; ks++) {
        ldmKA(kh[ks], s_kh, w * 16, ks * 16, lane);
        ldmKA(kl[ks], s_kl, w * 16, ks * 16, lane);
    }

    float O[8][4];
    #pragma unroll
    for (int nt = 0; nt < 8; nt++)
        #pragma unroll
        for (int j = 0; j < 4; j++) O[nt][j] = 0.f;
    float m0 = NEG_INF, m1 = NEG_INF, l0 = 0.f, l1 = 0.f;

    for (int c = 0; c <= tchunk; c++) {
        __syncthreads();   // protect Q/V smem from previous iteration's readers
        {
            const float* qsrc = kqv + (size_t)(b * T_ + c * 64 + row) * N3 + D_ + h * HD_ + half * 32;
            cvstore_tile(qsrc,       p_qh, p_ql, row, half);
            cvstore_tile(qsrc + D_,  p_vh, p_vl, row, half);
        }
        __syncthreads();

        // ---- S = K . Q^T (bf16x3) ----
        float sa[8][4];
        #pragma unroll
        for (int nt = 0; nt < 8; nt++)
            #pragma unroll
            for (int j = 0; j < 4; j++) sa[nt][j] = 0.f;

        #pragma unroll
        for (int ks = 0; ks < 4; ks++) {
            uint32_t bq[8][2];
            #pragma unroll
            for (int np = 0; np < 4; np++)
                ldmQB(bq[2 * np], bq[2 * np + 1], s_qh, np * 16, ks * 16, lane);
            #pragma unroll
            for (int nt = 0; nt < 8; nt++) mma_bf16(sa[nt], kh[ks], bq[nt]);
            #pragma unroll
            for (int nt = 0; nt < 8; nt++) mma_bf16(sa[nt], kl[ks], bq[nt]);
            #pragma unroll
            for (int np = 0; np < 4; np++)
                ldmQB(bq[2 * np], bq[2 * np + 1], s_ql, np * 16, ks * 16, lane);
            #pragma unroll
            for (int nt = 0; nt < 8; nt++) mma_bf16(sa[nt], kh[ks], bq[nt]);
        }

        // ---- causal mask on diagonal chunk ----
        if (c == tchunk) {
            int r0 = w * 16 + (lane >> 2);
            #pragma unroll
            for (int nt = 0; nt < 8; nt++) {
                int s0 = nt * 8 + (lane & 3) * 2;
                if (s0 + 0 > r0)     sa[nt][0] = NEG_INF;
                if (s0 + 1 > r0)     sa[nt][1] = NEG_INF;
                if (s0 + 0 > r0 + 8) sa[nt][2] = NEG_INF;
                if (s0 + 1 > r0 + 8) sa[nt][3] = NEG_INF;
            }
        }

        // ---- online softmax ----
        float cm0 = NEG_INF, cm1 = NEG_INF;
        #pragma unroll
        for (int nt = 0; nt < 8; nt++) {
            cm0 = fmaxf(cm0, fmaxf(sa[nt][0], sa[nt][1]));
            cm1 = fmaxf(cm1, fmaxf(sa[nt][2], sa[nt][3]));
        }
        cm0 = fmaxf(cm0, __shfl_xor_sync(0xffffffffu, cm0, 1));
        cm0 = fmaxf(cm0, __shfl_xor_sync(0xffffffffu, cm0, 2));
        cm1 = fmaxf(cm1, __shfl_xor_sync(0xffffffffu, cm1, 1));
        cm1 = fmaxf(cm1, __shfl_xor_sync(0xffffffffu, cm1, 2));

        float mn0 = fmaxf(m0, cm0), mn1 = fmaxf(m1, cm1);
        float al0 = __expf(m0 - mn0), al1 = __expf(m1 - mn1);
        m0 = mn0; m1 = mn1;
        l0 *= al0; l1 *= al1;
        #pragma unroll
        for (int nt = 0; nt < 8; nt++) {
            O[nt][0] *= al0; O[nt][1] *= al0;
            O[nt][2] *= al1; O[nt][3] *= al1;
        }

        #pragma unroll
        for (int nt = 0; nt < 8; nt++) {
            sa[nt][0] = __expf(sa[nt][0] - m0);
            sa[nt][1] = __expf(sa[nt][1] - m0);
            sa[nt][2] = __expf(sa[nt][2] - m1);
            sa[nt][3] = __expf(sa[nt][3] - m1);
            l0 += sa[nt][0] + sa[nt][1];
            l1 += sa[nt][2] + sa[nt][3];
        }

        // ---- O += P . V (bf16x3) ----
        #pragma unroll
        for (int ks = 0; ks < 4; ks++) {
            // P fragments for k-step ks: ntiles 2ks (k0-7), 2ks+1 (k8-15)
            uint32_t ah[4], al[4];
            #pragma unroll
            for (int q = 0; q < 2; q++) {      // q=0 -> rows r, regs a0/a2; q=1 -> rows r+8
                float p0 = sa[2 * ks][2 * q],     p1 = sa[2 * ks][2 * q + 1];
                float p2 = sa[2 * ks + 1][2 * q], p3 = sa[2 * ks + 1][2 * q + 1];
                __nv_bfloat16 h0 = __float2bfloat16_rn(p0), h1 = __float2bfloat16_rn(p1);
                __nv_bfloat16 h2 = __float2bfloat16_rn(p2), h3 = __float2bfloat16_rn(p3);
                __nv_bfloat16 e0 = __float2bfloat16_rn(p0 - __bfloat162float(h0));
                __nv_bfloat16 e1 = __float2bfloat16_rn(p1 - __bfloat162float(h1));
                __nv_bfloat16 e2 = __float2bfloat16_rn(p2 - __bfloat162float(h2));
                __nv_bfloat16 e3 = __float2bfloat16_rn(p3 - __bfloat162float(h3));
                ah[q]     = (unsigned)__bfloat16_as_ushort(h0) | ((unsigned)__bfloat16_as_ushort(h1) << 16);
                ah[q + 2] = (unsigned)__bfloat16_as_ushort(h2) | ((unsigned)__bfloat16_as_ushort(h3) << 16);
                al[q]     = (unsigned)__bfloat16_as_ushort(e0) | ((unsigned)__bfloat16_as_ushort(e1) << 16);
                al[q + 2] = (unsigned)__bfloat16_as_ushort(e2) | ((unsigned)__bfloat16_as_ushort(e3) << 16);
            }
            uint32_t bv[8][2];
            #pragma unroll
            for (int np = 0; np < 4; np++)
                ldmVB(bv[2 * np], bv[2 * np + 1], s_vh, ks * 16, np * 16, lane);
            #pragma unroll
            for (int nt = 0; nt < 8; nt++) mma_bf16(O[nt], ah, bv[nt]);
            #pragma unroll
            for (int nt = 0; nt < 8; nt++) mma_bf16(O[nt], al, bv[nt]);
            #pragma unroll
            for (int np = 0; np < 4; np++)
                ldmVB(bv[2 * np], bv[2 * np + 1], s_vl, ks * 16, np * 16, lane);
            #pragma unroll
            for (int nt = 0; nt < 8; nt++) mma_bf16(O[nt], ah, bv[nt]);
        }
    }

    // ---- epilogue ----
    l0 += __shfl_xor_sync(0xffffffffu, l0, 1);
    l0 += __shfl_xor_sync(0xffffffffu, l0, 2);
    l1 += __shfl_xor_sync(0xffffffffu, l1, 1);
    l1 += __shfl_xor_sync(0xffffffffu, l1, 2);
    float inv0 = 1.f / l0, inv1 = 1.f / l1;

    int r0 = tbase + w * 16 + (lane >> 2);
    #pragma unroll
    for (int nt = 0; nt < 8; nt++) {
        int col = h * HD_ + nt * 8 + (lane & 3) * 2;
        *(float2*)(out + (size_t)(b * T_ + r0) * D_ + col) =
            make_float2(O[nt][0] * inv0, O[nt][1] * inv0);
        *(float2*)(out + (size_t)(b * T_ + r0 + 8) * D_ + col) =
            make_float2(O[nt][2] * inv1, O[nt][3] * inv1);
    }
}

// ---------------- launch ----------------
extern "C" void kernel_launch(void* const* d_in, const int* in_sizes, int n_in,
                              void* d_out, int out_size) {
    const float* x  = (const float*)d_in[0];
    const float* Wi = (const float*)d_in[1];
    const float* bi = (const float*)d_in[2];
    const float* Wk = (const float*)d_in[3];
    const float* bk = (const float*)d_in[4];
    const float* Wq = (const float*)d_in[5];
    const float* bq = (const float*)d_in[6];
    const float* Wv = (const float*)d_in[7];
    const float* bv = (const float*)d_in[8];
    const float* Wo = (const float*)d_in[9];
    const float* bo = (const float*)d_in[10];
    float* out = (float*)d_out;

    float *p_h, *p_kqv, *p_attn, *p_wkqv, *p_bkqv;
    cudaGetSymbolAddress((void**)&p_h,    g_h);
    cudaGetSymbolAddress((void**)&p_kqv,  g_kqv);
    cudaGetSymbolAddress((void**)&p_attn, g_attn);
    cudaGetSymbolAddress((void**)&p_wkqv, g_wkqv);
    cudaGetSymbolAddress((void**)&p_bkqv, g_bkqv);

    static bool attr_set = false;
    if (!attr_set) {
        cudaFuncSetAttribute(gemm_bf16x3, cudaFuncAttributeMaxDynamicSharedMemorySize, GEMM_SMEM);
        attr_set = true;
    }

    repack_kernel<<<(3 * H_ * D_ * HD_ + 255) / 256, 256>>>(Wk, Wq, Wv, bk, bq, bv);

    {   // h = x @ Wi + bi
        dim3 grid(D_ / BN, M_ / BM);
        gemm_bf16x3<<<grid, 256, GEMM_SMEM>>>(M_, D_, D_, x, Wi, bi, p_h);
    }
    {   // kqv = h @ Wkqv + bkqv
        dim3 grid(N3 / BN, M_ / BM);
        gemm_bf16x3<<<grid, 256, GEMM_SMEM>>>(M_, N3, D_, p_h, p_wkqv, p_bkqv, p_kqv);
    }
    {   // fused causal attention (tensor cores)
        dim3 grid(T_ / 64, H_, B_);
        attn_tc<<<grid, 128>>>(p_kqv, p_attn);
    }
    {   // out = attn @ Wo + bo
        dim3 grid(D_ / BN, M_ / BM);
        gemm_bf16x3<<<grid, 256, GEMM_SMEM>>>(M_, D_, D_, p_attn, Wo, bo, out);
    }
}

// round 6
// speedup vs baseline: 2.4881x; 1.1440x over previous
#include <cuda_runtime.h>
#include <cuda_bf16.h>
#include <math.h>
#include <stdint.h>

#define B_  32
#define T_  512
#define D_  1024
#define H_  16
#define HD_ 64
#define M_  (B_ * T_)      // 16384
#define N3  (3 * D_)       // 3072

#define NEG_INF __int_as_float(0xff800000)

typedef __nv_bfloat16 bf16;

// ---------------- device scratch ----------------
__device__ bf16 g_xh[M_ * D_],   g_xl[M_ * D_];
__device__ bf16 g_hh[M_ * D_],   g_hl[M_ * D_];
__device__ bf16 g_kqvh[M_ * N3], g_kqvl[M_ * N3];
__device__ bf16 g_ah[M_ * D_],   g_al[M_ * D_];
__device__ bf16 g_wih[D_ * D_],  g_wil[D_ * D_];
__device__ bf16 g_wkh[D_ * N3],  g_wkl[D_ * N3];
__device__ bf16 g_woh[D_ * D_],  g_wol[D_ * D_];
__device__ float g_bkqv[N3];

__device__ __forceinline__ void split1(float v, bf16& h, bf16& l) {
    h = __float2bfloat16_rn(v);
    l = __float2bfloat16_rn(v - __bfloat162float(h));
}

// ---------------- generic fp32 -> hi/lo bf16 split ----------------
__global__ void split_kernel(const float* __restrict__ src, bf16* __restrict__ dh,
                             bf16* __restrict__ dl, int n) {
    int i = (blockIdx.x * blockDim.x + threadIdx.x) * 4;
    if (i >= n) return;
    float4 v = *(const float4*)(src + i);
    bf16 h0, l0, h1, l1, h2, l2, h3, l3;
    split1(v.x, h0, l0); split1(v.y, h1, l1);
    split1(v.z, h2, l2); split1(v.w, h3, l3);
    uint32_t hh0 = (uint32_t)__bfloat16_as_ushort(h0) | ((uint32_t)__bfloat16_as_ushort(h1) << 16);
    uint32_t hh1 = (uint32_t)__bfloat16_as_ushort(h2) | ((uint32_t)__bfloat16_as_ushort(h3) << 16);
    uint32_t ll0 = (uint32_t)__bfloat16_as_ushort(l0) | ((uint32_t)__bfloat16_as_ushort(l1) << 16);
    uint32_t ll1 = (uint32_t)__bfloat16_as_ushort(l2) | ((uint32_t)__bfloat16_as_ushort(l3) << 16);
    *(uint2*)(dh + i) = make_uint2(hh0, hh1);
    *(uint2*)(dl + i) = make_uint2(ll0, ll1);
}

// ---------------- weight repack + split: [H,D,HD]x3 -> [D, 3072] hi/lo ----------------
__global__ void repack_split_kernel(const float* __restrict__ Wk, const float* __restrict__ Wq,
                                    const float* __restrict__ Wv, const float* __restrict__ bk,
                                    const float* __restrict__ bq, const float* __restrict__ bv) {
    int idx = blockIdx.x * blockDim.x + threadIdx.x;
    const int per = H_ * D_ * HD_;
    if (idx < 3 * per) {
        int w  = idx / per;
        int r  = idx % per;
        int h  = r / (D_ * HD_);
        int r2 = r % (D_ * HD_);
        int d  = r2 / HD_;
        int e  = r2 % HD_;
        const float* src = (w == 0) ? Wk : ((w == 1) ? Wq : Wv);
        float v = src[h * D_ * HD_ + d * HD_ + e];
        bf16 hh, ll;
        split1(v, hh, ll);
        int o = d * N3 + w * D_ + h * HD_ + e;
        g_wkh[o] = hh;
        g_wkl[o] = ll;
    }
    if (idx < N3) {
        int w = idx / D_;
        int c = idx % D_;
        const float* bsrc = (w == 0) ? bk : ((w == 1) ? bq : bv);
        g_bkqv[idx] = bsrc[c];
    }
}

// ---------------- MMA / ldmatrix helpers ----------------
__device__ __forceinline__ void mma_bf16(float* d, const uint32_t* a, const uint32_t* b) {
    asm volatile("mma.sync.aligned.m16n8k16.row.col.f32.bf16.bf16.f32 "
                 "{%0,%1,%2,%3}, {%4,%5,%6,%7}, {%8,%9}, {%0,%1,%2,%3};"
                 : "+f"(d[0]), "+f"(d[1]), "+f"(d[2]), "+f"(d[3])
                 : "r"(a[0]), "r"(a[1]), "r"(a[2]), "r"(a[3]), "r"(b[0]), "r"(b[1]));
}

__device__ __forceinline__ void cp16(uint32_t dst, const void* src) {
    asm volatile("cp.async.cg.shared.global [%0], [%1], 16;" :: "r"(dst), "l"(src));
}
__device__ __forceinline__ void cp_commit() { asm volatile("cp.async.commit_group;"); }
template <int N> __device__ __forceinline__ void cp_wait() {
    asm volatile("cp.async.wait_group %0;" :: "n"(N));
}

// =======================================================================
// GEMM on pre-split hi/lo bf16: C = (Ah+Al)(Bh+Bl) ~ AhBh + AlBh + AhBl
// Tile 128x128x32, 256 threads, 2 CTAs/SM, cp.async double buffer.
// smem/stage: A 128 rows x 128B (hi 4 chunks | lo 4 chunks, XOR swizzle),
//             B 32 rows x 512B (hi 16 chunks | lo 16 chunks, XOR swizzle).
// =======================================================================
#define GBM 128
#define GBN 128
#define GBK 32
#define SA_OFF 0
#define SB_OFF 16384
#define STAGE 32768
#define GEMM_SMEM (2 * STAGE)

__device__ __forceinline__ void g_ldmA(uint32_t* r, uint32_t sA, int m0, int kk, int hl, int lane) {
    int mrow  = m0 + (lane & 7) + ((lane >> 3) & 1) * 8;
    int chunk = ((kk >> 3) + (lane >> 4) + hl * 4) ^ (mrow & 7);
    uint32_t addr = sA + mrow * 128 + chunk * 16;
    asm volatile("ldmatrix.sync.aligned.m8n8.x4.shared.b16 {%0,%1,%2,%3}, [%4];"
                 : "=r"(r[0]), "=r"(r[1]), "=r"(r[2]), "=r"(r[3]) : "r"(addr));
}

__device__ __forceinline__ void g_ldmB(uint32_t* b0, uint32_t* b1, uint32_t sB,
                                       int kk, int nb, int hl, int lane) {
    int krow  = kk + (lane & 7) + ((lane >> 3) & 1) * 8;
    int nc    = nb + (lane >> 4) * 8;
    int chunk = (((nc >> 3) ^ (krow & 7)) + hl * 16);
    uint32_t addr = sB + krow * 512 + chunk * 16;
    uint32_t r0, r1, r2, r3;
    asm volatile("ldmatrix.sync.aligned.m8n8.x4.trans.shared.b16 {%0,%1,%2,%3}, [%4];"
                 : "=r"(r0), "=r"(r1), "=r"(r2), "=r"(r3) : "r"(addr));
    b0[0] = r0; b0[1] = r1; b1[0] = r2; b1[1] = r3;
}

// OM: 0 = fp32 C, 1 = hi/lo bf16 C
template <int OM>
__global__ void __launch_bounds__(256, 2)
gemm_pre(int M, int N, int K,
         const bf16* __restrict__ Ah, const bf16* __restrict__ Al,
         const bf16* __restrict__ Bh, const bf16* __restrict__ Bl,
         const float* __restrict__ bias, float* __restrict__ C,
         bf16* __restrict__ Ch, bf16* __restrict__ Cl) {
    extern __shared__ char sm[];
    const int tid = threadIdx.x, lane = tid & 31, wid = tid >> 5;
    const int bm = blockIdx.y, bn = blockIdx.x;
    const int warp_m = wid >> 2, warp_n = wid & 3;
    uint32_t sbase = (uint32_t)__cvta_generic_to_shared(sm);

    // cp.async mappings
    const int aRow = tid >> 1, aHL = tid & 1;          // A: row, hi/lo
    const int bKr  = tid >> 3, bPiece = tid & 7;       // B: k-row, piece
    const int bHL  = bPiece >> 2, bQ = bPiece & 3;

    const bf16* Asrc = (aHL ? Al : Ah) + (size_t)(bm * GBM + aRow) * K;
    const bf16* Bsrc = (bHL ? Bl : Bh) + (size_t)bKr * N + bn * GBN;

    auto issue_stage = [&](int buf, int kt) {
        uint32_t sA = sbase + buf * STAGE + SA_OFF;
        uint32_t sB = sbase + buf * STAGE + SB_OFF;
        const bf16* a = Asrc + kt * GBK;
        #pragma unroll
        for (int j = 0; j < 4; j++) {
            int chunk = ((aHL * 4 + j) ^ (aRow & 7));
            cp16(sA + aRow * 128 + chunk * 16, a + j * 8);
        }
        const bf16* b = Bsrc + (size_t)kt * GBK * N;
        #pragma unroll
        for (int i = 0; i < 4; i++) {
            int c0 = bQ * 4 + i;
            int chunk = (c0 ^ (bKr & 7)) + bHL * 16;
            cp16(sB + bKr * 512 + chunk * 16, b + c0 * 8);
        }
        cp_commit();
    };

    float acc[4][4][4] = {};
    const int NT = K / GBK;

    issue_stage(0, 0);

    for (int kt = 0; kt < NT; kt++) {
        int cur = kt & 1;
        if (kt + 1 < NT) { issue_stage(cur ^ 1, kt + 1); cp_wait<1>(); }
        else             { cp_wait<0>(); }
        __syncthreads();

        uint32_t sA = sbase + cur * STAGE + SA_OFF;
        uint32_t sB = sbase + cur * STAGE + SB_OFF;

        #pragma unroll
        for (int kk = 0; kk < GBK; kk += 16) {
            uint32_t bh[4][2], bl[4][2];
            g_ldmB(bh[0], bh[1], sB, kk, warp_n * 32,      0, lane);
            g_ldmB(bh[2], bh[3], sB, kk, warp_n * 32 + 16, 0, lane);
            g_ldmB(bl[0], bl[1], sB, kk, warp_n * 32,      1, lane);
            g_ldmB(bl[2], bl[3], sB, kk, warp_n * 32 + 16, 1, lane);
            #pragma unroll
            for (int mt = 0; mt < 4; mt++) {
                uint32_t ah[4], al[4];
                g_ldmA(ah, sA, warp_m * 64 + mt * 16, kk, 0, lane);
                g_ldmA(al, sA, warp_m * 64 + mt * 16, kk, 1, lane);
                #pragma unroll
                for (int nt = 0; nt < 4; nt++) mma_bf16(acc[mt][nt], ah, bh[nt]);
                #pragma unroll
                for (int nt = 0; nt < 4; nt++) mma_bf16(acc[mt][nt], al, bh[nt]);
                #pragma unroll
                for (int nt = 0; nt < 4; nt++) mma_bf16(acc[mt][nt], ah, bl[nt]);
            }
        }
        __syncthreads();
    }

    #pragma unroll
    for (int mt = 0; mt < 4; mt++) {
        int r0 = bm * GBM + warp_m * 64 + mt * 16 + (lane >> 2);
        #pragma unroll
        for (int nt = 0; nt < 4; nt++) {
            int c = bn * GBN + warp_n * 32 + nt * 8 + (lane & 3) * 2;
            float2 b2 = *(const float2*)(bias + c);
            float v00 = acc[mt][nt][0] + b2.x, v01 = acc[mt][nt][1] + b2.y;
            float v10 = acc[mt][nt][2] + b2.x, v11 = acc[mt][nt][3] + b2.y;
            if (OM == 0) {
                *(float2*)(C + (size_t)r0 * N + c)       = make_float2(v00, v01);
                *(float2*)(C + (size_t)(r0 + 8) * N + c) = make_float2(v10, v11);
            } else {
                bf16 h0, l0, h1, l1;
                split1(v00, h0, l0); split1(v01, h1, l1);
                *(uint32_t*)(Ch + (size_t)r0 * N + c) =
                    (uint32_t)__bfloat16_as_ushort(h0) | ((uint32_t)__bfloat16_as_ushort(h1) << 16);
                *(uint32_t*)(Cl + (size_t)r0 * N + c) =
                    (uint32_t)__bfloat16_as_ushort(l0) | ((uint32_t)__bfloat16_as_ushort(l1) << 16);
                split1(v10, h0, l0); split1(v11, h1, l1);
                *(uint32_t*)(Ch + (size_t)(r0 + 8) * N + c) =
                    (uint32_t)__bfloat16_as_ushort(h0) | ((uint32_t)__bfloat16_as_ushort(h1) << 16);
                *(uint32_t*)(Cl + (size_t)(r0 + 8) * N + c) =
                    (uint32_t)__bfloat16_as_ushort(l0) | ((uint32_t)__bfloat16_as_ushort(l1) << 16);
            }
        }
    }
}

// =======================================================================
// Tensor-core flash attention on pre-split bf16 kqv
// =======================================================================
#define ATT_MAT 8192

__device__ __forceinline__ void ldmKA(uint32_t* r, uint32_t base, int m0, int kk, int lane) {
    int mrow  = m0 + (lane & 7) + ((lane >> 3) & 1) * 8;
    int chunk = ((kk >> 3) + (lane >> 4)) ^ (mrow & 7);
    uint32_t addr = base + mrow * 128 + chunk * 16;
    asm volatile("ldmatrix.sync.aligned.m8n8.x4.shared.b16 {%0,%1,%2,%3}, [%4];"
                 : "=r"(r[0]), "=r"(r[1]), "=r"(r[2]), "=r"(r[3]) : "r"(addr));
}

__device__ __forceinline__ void ldmQB(uint32_t* t0, uint32_t* t1, uint32_t base,
                                      int n0, int kk, int lane) {
    int g     = lane >> 3;
    int nrow  = n0 + (lane & 7) + (g >> 1) * 8;
    int chunk = ((kk >> 3) + (g & 1)) ^ (nrow & 7);
    uint32_t addr = base + nrow * 128 + chunk * 16;
    uint32_t r0, r1, r2, r3;
    asm volatile("ldmatrix.sync.aligned.m8n8.x4.shared.b16 {%0,%1,%2,%3}, [%4];"
                 : "=r"(r0), "=r"(r1), "=r"(r2), "=r"(r3) : "r"(addr));
    t0[0] = r0; t0[1] = r1; t1[0] = r2; t1[1] = r3;
}

__device__ __forceinline__ void ldmVB(uint32_t* t0, uint32_t* t1, uint32_t base,
                                      int kk, int nb, int lane) {
    int krow  = kk + (lane & 7) + ((lane >> 3) & 1) * 8;
    int nc    = nb + (lane >> 4) * 8;
    int chunk = (nc >> 3) ^ (krow & 7);
    uint32_t addr = base + krow * 128 + chunk * 16;
    uint32_t r0, r1, r2, r3;
    asm volatile("ldmatrix.sync.aligned.m8n8.x4.trans.shared.b16 {%0,%1,%2,%3}, [%4];"
                 : "=r"(r0), "=r"(r1), "=r"(r2), "=r"(r3) : "r"(addr));
    t0[0] = r0; t0[1] = r1; t1[0] = r2; t1[1] = r3;
}

// copy one row-half (32 bf16 = 2 chunks x 16B... actually 4 chunks of 8 bf16)
__device__ __forceinline__ void copy_half_row(const bf16* __restrict__ src,
                                              char* dst_base, int row, int half) {
    #pragma unroll
    for (int j = 0; j < 4; j++) {
        int chunk = (half * 4 + j) ^ (row & 7);
        *(uint4*)(dst_base + row * 128 + chunk * 16) = *(const uint4*)(src + j * 8);
    }
}

__global__ void __launch_bounds__(128)
attn_tc(const bf16* __restrict__ kqvh, const bf16* __restrict__ kqvl,
        bf16* __restrict__ outh, bf16* __restrict__ outl) {
    __shared__ __align__(16) char smem[6 * ATT_MAT];
    char* p_kh = smem;
    char* p_kl = smem + ATT_MAT;
    char* p_qh = smem + 2 * ATT_MAT;
    char* p_ql = smem + 3 * ATT_MAT;
    char* p_vh = smem + 4 * ATT_MAT;
    char* p_vl = smem + 5 * ATT_MAT;

    const int tid = threadIdx.x, lane = tid & 31, w = tid >> 5;
    const int tchunk = blockIdx.x, h = blockIdx.y, b = blockIdx.z;
    const int tbase = tchunk * 64;

    uint32_t sb = (uint32_t)__cvta_generic_to_shared(smem);
    uint32_t s_kh = sb,               s_kl = sb + ATT_MAT;
    uint32_t s_qh = sb + 2 * ATT_MAT, s_ql = sb + 3 * ATT_MAT;
    uint32_t s_vh = sb + 4 * ATT_MAT, s_vl = sb + 5 * ATT_MAT;

    const int row  = tid >> 1;
    const int half = tid & 1;

    {
        size_t off = (size_t)(b * T_ + tbase + row) * N3 + h * HD_ + half * 32;
        copy_half_row(kqvh + off, p_kh, row, half);
        copy_half_row(kqvl + off, p_kl, row, half);
    }
    __syncthreads();

    uint32_t kh[4][4], kl[4][4];
    #pragma unroll
    for (int ks = 0; ks < 4; ks++) {
        ldmKA(kh[ks], s_kh, w * 16, ks * 16, lane);
        ldmKA(kl[ks], s_kl, w * 16, ks * 16, lane);
    }

    float O[8][4];
    #pragma unroll
    for (int nt = 0; nt < 8; nt++)
        #pragma unroll
        for (int j = 0; j < 4; j++) O[nt][j] = 0.f;
    float m0 = NEG_INF, m1 = NEG_INF, l0 = 0.f, l1 = 0.f;

    for (int c = 0; c <= tchunk; c++) {
        __syncthreads();
        {
            size_t off = (size_t)(b * T_ + c * 64 + row) * N3 + D_ + h * HD_ + half * 32;
            copy_half_row(kqvh + off,      p_qh, row, half);
            copy_half_row(kqvl + off,      p_ql, row, half);
            copy_half_row(kqvh + off + D_, p_vh, row, half);
            copy_half_row(kqvl + off + D_, p_vl, row, half);
        }
        __syncthreads();

        float sa[8][4];
        #pragma unroll
        for (int nt = 0; nt < 8; nt++)
            #pragma unroll
            for (int j = 0; j < 4; j++) sa[nt][j] = 0.f;

        #pragma unroll
        for (int ks = 0; ks < 4; ks++) {
            uint32_t bq[8][2];
            #pragma unroll
            for (int np = 0; np < 4; np++)
                ldmQB(bq[2 * np], bq[2 * np + 1], s_qh, np * 16, ks * 16, lane);
            #pragma unroll
            for (int nt = 0; nt < 8; nt++) mma_bf16(sa[nt], kh[ks], bq[nt]);
            #pragma unroll
            for (int nt = 0; nt < 8; nt++) mma_bf16(sa[nt], kl[ks], bq[nt]);
            #pragma unroll
            for (int np = 0; np < 4; np++)
                ldmQB(bq[2 * np], bq[2 * np + 1], s_ql, np * 16, ks * 16, lane);
            #pragma unroll
            for (int nt = 0; nt < 8; nt++) mma_bf16(sa[nt], kh[ks], bq[nt]);
        }

        if (c == tchunk) {
            int r0 = w * 16 + (lane >> 2);
            #pragma unroll
            for (int nt = 0; nt < 8; nt++) {
                int s0 = nt * 8 + (lane & 3) * 2;
                if (s0 + 0 > r0)     sa[nt][0] = NEG_INF;
                if (s0 + 1 > r0)     sa[nt][1] = NEG_INF;
                if (s0 + 0 > r0 + 8) sa[nt][2] = NEG_INF;
                if (s0 + 1 > r0 + 8) sa[nt][3] = NEG_INF;
            }
        }

        float cm0 = NEG_INF, cm1 = NEG_INF;
        #pragma unroll
        for (int nt = 0; nt < 8; nt++) {
            cm0 = fmaxf(cm0, fmaxf(sa[nt][0], sa[nt][1]));
            cm1 = fmaxf(cm1, fmaxf(sa[nt][2], sa[nt][3]));
        }
        cm0 = fmaxf(cm0, __shfl_xor_sync(0xffffffffu, cm0, 1));
        cm0 = fmaxf(cm0, __shfl_xor_sync(0xffffffffu, cm0, 2));
        cm1 = fmaxf(cm1, __shfl_xor_sync(0xffffffffu, cm1, 1));
        cm1 = fmaxf(cm1, __shfl_xor_sync(0xffffffffu, cm1, 2));

        float mn0 = fmaxf(m0, cm0), mn1 = fmaxf(m1, cm1);
        float al0 = __expf(m0 - mn0), al1 = __expf(m1 - mn1);
        m0 = mn0; m1 = mn1;
        l0 *= al0; l1 *= al1;
        #pragma unroll
        for (int nt = 0; nt < 8; nt++) {
            O[nt][0] *= al0; O[nt][1] *= al0;
            O[nt][2] *= al1; O[nt][3] *= al1;
        }

        #pragma unroll
        for (int nt = 0; nt < 8; nt++) {
            sa[nt][0] = __expf(sa[nt][0] - m0);
            sa[nt][1] = __expf(sa[nt][1] - m0);
            sa[nt][2] = __expf(sa[nt][2] - m1);
            sa[nt][3] = __expf(sa[nt][3] - m1);
            l0 += sa[nt][0] + sa[nt][1];
            l1 += sa[nt][2] + sa[nt][3];
        }

        #pragma unroll
        for (int ks = 0; ks < 4; ks++) {
            uint32_t ah[4], al[4];
            #pragma unroll
            for (int q = 0; q < 2; q++) {
                float p0 = sa[2 * ks][2 * q],     p1 = sa[2 * ks][2 * q + 1];
                float p2 = sa[2 * ks + 1][2 * q], p3 = sa[2 * ks + 1][2 * q + 1];
                bf16 h0, e0, h1, e1, h2, e2, h3, e3;
                split1(p0, h0, e0); split1(p1, h1, e1);
                split1(p2, h2, e2); split1(p3, h3, e3);
                ah[q]     = (uint32_t)__bfloat16_as_ushort(h0) | ((uint32_t)__bfloat16_as_ushort(h1) << 16);
                ah[q + 2] = (uint32_t)__bfloat16_as_ushort(h2) | ((uint32_t)__bfloat16_as_ushort(h3) << 16);
                al[q]     = (uint32_t)__bfloat16_as_ushort(e0) | ((uint32_t)__bfloat16_as_ushort(e1) << 16);
                al[q + 2] = (uint32_t)__bfloat16_as_ushort(e2) | ((uint32_t)__bfloat16_as_ushort(e3) << 16);
            }
            uint32_t bv[8][2];
            #pragma unroll
            for (int np = 0; np < 4; np++)
                ldmVB(bv[2 * np], bv[2 * np + 1], s_vh, ks * 16, np * 16, lane);
            #pragma unroll
            for (int nt = 0; nt < 8; nt++) mma_bf16(O[nt], ah, bv[nt]);
            #pragma unroll
            for (int nt = 0; nt < 8; nt++) mma_bf16(O[nt], al, bv[nt]);
            #pragma unroll
            for (int np = 0; np < 4; np++)
                ldmVB(bv[2 * np], bv[2 * np + 1], s_vl, ks * 16, np * 16, lane);
            #pragma unroll
            for (int nt = 0; nt < 8; nt++) mma_bf16(O[nt], ah, bv[nt]);
        }
    }

    l0 += __shfl_xor_sync(0xffffffffu, l0, 1);
    l0 += __shfl_xor_sync(0xffffffffu, l0, 2);
    l1 += __shfl_xor_sync(0xffffffffu, l1, 1);
    l1 += __shfl_xor_sync(0xffffffffu, l1, 2);
    float inv0 = 1.f / l0, inv1 = 1.f / l1;

    int r0 = tbase + w * 16 + (lane >> 2);
    #pragma unroll
    for (int nt = 0; nt < 8; nt++) {
        int col = h * HD_ + nt * 8 + (lane & 3) * 2;
        float v00 = O[nt][0] * inv0, v01 = O[nt][1] * inv0;
        float v10 = O[nt][2] * inv1, v11 = O[nt][3] * inv1;
        bf16 h0, e0, h1, e1;
        split1(v00, h0, e0); split1(v01, h1, e1);
        *(uint32_t*)(outh + (size_t)(b * T_ + r0) * D_ + col) =
            (uint32_t)__bfloat16_as_ushort(h0) | ((uint32_t)__bfloat16_as_ushort(h1) << 16);
        *(uint32_t*)(outl + (size_t)(b * T_ + r0) * D_ + col) =
            (uint32_t)__bfloat16_as_ushort(e0) | ((uint32_t)__bfloat16_as_ushort(e1) << 16);
        split1(v10, h0, e0); split1(v11, h1, e1);
        *(uint32_t*)(outh + (size_t)(b * T_ + r0 + 8) * D_ + col) =
            (uint32_t)__bfloat16_as_ushort(h0) | ((uint32_t)__bfloat16_as_ushort(h1) << 16);
        *(uint32_t*)(outl + (size_t)(b * T_ + r0 + 8) * D_ + col) =
            (uint32_t)__bfloat16_as_ushort(e0) | ((uint32_t)__bfloat16_as_ushort(e1) << 16);
    }
}

// ---------------- launch ----------------
extern "C" void kernel_launch(void* const* d_in, const int* in_sizes, int n_in,
                              void* d_out, int out_size) {
    const float* x  = (const float*)d_in[0];
    const float* Wi = (const float*)d_in[1];
    const float* bi = (const float*)d_in[2];
    const float* Wk = (const float*)d_in[3];
    const float* bk = (const float*)d_in[4];
    const float* Wq = (const float*)d_in[5];
    const float* bq = (const float*)d_in[6];
    const float* Wv = (const float*)d_in[7];
    const float* bv = (const float*)d_in[8];
    const float* Wo = (const float*)d_in[9];
    const float* bo = (const float*)d_in[10];
    float* out = (float*)d_out;

    bf16 *p_xh, *p_xl, *p_hh, *p_hl, *p_kqvh, *p_kqvl, *p_ah, *p_al;
    bf16 *p_wih, *p_wil, *p_wkh, *p_wkl, *p_woh, *p_wol;
    float* p_bkqv;
    cudaGetSymbolAddress((void**)&p_xh, g_xh);     cudaGetSymbolAddress((void**)&p_xl, g_xl);
    cudaGetSymbolAddress((void**)&p_hh, g_hh);     cudaGetSymbolAddress((void**)&p_hl, g_hl);
    cudaGetSymbolAddress((void**)&p_kqvh, g_kqvh); cudaGetSymbolAddress((void**)&p_kqvl, g_kqvl);
    cudaGetSymbolAddress((void**)&p_ah, g_ah);     cudaGetSymbolAddress((void**)&p_al, g_al);
    cudaGetSymbolAddress((void**)&p_wih, g_wih);   cudaGetSymbolAddress((void**)&p_wil, g_wil);
    cudaGetSymbolAddress((void**)&p_wkh, g_wkh);   cudaGetSymbolAddress((void**)&p_wkl, g_wkl);
    cudaGetSymbolAddress((void**)&p_woh, g_woh);   cudaGetSymbolAddress((void**)&p_wol, g_wol);
    cudaGetSymbolAddress((void**)&p_bkqv, g_bkqv);

    static bool attr_set = false;
    if (!attr_set) {
        cudaFuncSetAttribute(gemm_pre<0>, cudaFuncAttributeMaxDynamicSharedMemorySize, GEMM_SMEM);
        cudaFuncSetAttribute(gemm_pre<1>, cudaFuncAttributeMaxDynamicSharedMemorySize, GEMM_SMEM);
        attr_set = true;
    }

    // splits
    split_kernel<<<(M_ * D_ / 4 + 255) / 256, 256>>>(x,  p_xh,  p_xl,  M_ * D_);
    split_kernel<<<(D_ * D_ / 4 + 255) / 256, 256>>>(Wi, p_wih, p_wil, D_ * D_);
    split_kernel<<<(D_ * D_ / 4 + 255) / 256, 256>>>(Wo, p_woh, p_wol, D_ * D_);
    repack_split_kernel<<<(3 * H_ * D_ * HD_ + 255) / 256, 256>>>(Wk, Wq, Wv, bk, bq, bv);

    {   // h = x @ Wi + bi  -> hi/lo
        dim3 grid(D_ / GBN, M_ / GBM);
        gemm_pre<1><<<grid, 256, GEMM_SMEM>>>(M_, D_, D_, p_xh, p_xl, p_wih, p_wil,
                                              bi, nullptr, p_hh, p_hl);
    }
    {   // kqv = h @ Wkqv + bkqv -> hi/lo
        dim3 grid(N3 / GBN, M_ / GBM);
        gemm_pre<1><<<grid, 256, GEMM_SMEM>>>(M_, N3, D_, p_hh, p_hl, p_wkh, p_wkl,
                                              p_bkqv, nullptr, p_kqvh, p_kqvl);
    }
    {   // attention -> hi/lo
        dim3 grid(T_ / 64, H_, B_);
        attn_tc<<<grid, 128>>>(p_kqvh, p_kqvl, p_ah, p_al);
    }
    {   // out = attn @ Wo + bo -> fp32
        dim3 grid(D_ / GBN, M_ / GBM);
        gemm_pre<0><<<grid, 256, GEMM_SMEM>>>(M_, D_, D_, p_ah, p_al, p_woh, p_wol,
                                              bo, out, nullptr, nullptr);
    }
}

// round 9
// speedup vs baseline: 2.7176x; 1.0923x over previous
#include <cuda_runtime.h>
#include <cuda_bf16.h>
#include <math.h>
#include <stdint.h>

#define B_  32
#define T_  512
#define D_  1024
#define H_  16
#define HD_ 64
#define M_  (B_ * T_)      // 16384
#define N3  (3 * D_)       // 3072

#define NEG_INF __int_as_float(0xff800000)

typedef __nv_bfloat16 bf16;

// ---------------- device scratch ----------------
__device__ bf16 g_xh[M_ * D_],   g_xl[M_ * D_];
__device__ bf16 g_kqvh[M_ * N3], g_kqvl[M_ * N3];
__device__ bf16 g_ah[M_ * D_],   g_al[M_ * D_];
__device__ bf16 g_wih[D_ * D_],  g_wil[D_ * D_];    // Wi row-major [K][N]/[M][K]
__device__ bf16 g_wkh[D_ * N3],  g_wkl[D_ * N3];    // repacked Wkqv row-major [K][N]
__device__ bf16 g_wph[D_ * N3],  g_wpl[D_ * N3];    // fused W' = Wi@Wkqv, [K][N]
__device__ bf16 g_woh[D_ * D_],  g_wol[D_ * D_];    // Wo row-major [K][N]
__device__ float g_bkqv[N3];
__device__ float g_bfused[N3];
__device__ float g_zero[N3];     // stays zero

__device__ __forceinline__ void split1(float v, bf16& h, bf16& l) {
    h = __float2bfloat16_rn(v);
    l = __float2bfloat16_rn(v - __bfloat162float(h));
}

// ---------------- fp32 -> hi/lo bf16 split ----------------
__global__ void split_kernel(const float* __restrict__ src, bf16* __restrict__ dh,
                             bf16* __restrict__ dl, int n) {
    int i = (blockIdx.x * blockDim.x + threadIdx.x) * 4;
    if (i >= n) return;
    float4 v = *(const float4*)(src + i);
    bf16 h0, l0, h1, l1, h2, l2, h3, l3;
    split1(v.x, h0, l0); split1(v.y, h1, l1);
    split1(v.z, h2, l2); split1(v.w, h3, l3);
    uint32_t hh0 = (uint32_t)__bfloat16_as_ushort(h0) | ((uint32_t)__bfloat16_as_ushort(h1) << 16);
    uint32_t hh1 = (uint32_t)__bfloat16_as_ushort(h2) | ((uint32_t)__bfloat16_as_ushort(h3) << 16);
    uint32_t ll0 = (uint32_t)__bfloat16_as_ushort(l0) | ((uint32_t)__bfloat16_as_ushort(l1) << 16);
    uint32_t ll1 = (uint32_t)__bfloat16_as_ushort(l2) | ((uint32_t)__bfloat16_as_ushort(l3) << 16);
    *(uint2*)(dh + i) = make_uint2(hh0, hh1);
    *(uint2*)(dl + i) = make_uint2(ll0, ll1);
}

// ---------------- weight repack + split: [H,D,HD]x3 -> [D][3072] row-major hi/lo ----------------
__global__ void repack_split_kernel(const float* __restrict__ Wk, const float* __restrict__ Wq,
                                    const float* __restrict__ Wv, const float* __restrict__ bk,
                                    const float* __restrict__ bq, const float* __restrict__ bv) {
    int idx = blockIdx.x * blockDim.x + threadIdx.x;
    const int per = H_ * D_ * HD_;
    if (idx < 3 * per) {
        int w  = idx / per;
        int r  = idx % per;
        int h  = r / (D_ * HD_);
        int r2 = r % (D_ * HD_);
        int d  = r2 / HD_;
        int e  = r2 % HD_;
        const float* src = (w == 0) ? Wk : ((w == 1) ? Wq : Wv);
        float v = src[h * D_ * HD_ + d * HD_ + e];
        bf16 hh, ll;
        split1(v, hh, ll);
        int o = d * N3 + w * D_ + h * HD_ + e;
        g_wkh[o] = hh;
        g_wkl[o] = ll;
    }
    if (idx < N3) {
        int w = idx / D_;
        int c = idx % D_;
        const float* bsrc = (w == 0) ? bk : ((w == 1) ? bq : bv);
        g_bkqv[idx] = bsrc[c];
    }
}

// ---------------- fused bias: b' = bi @ Wkqv + bkqv ----------------
__global__ void bias_fuse_kernel(const float* __restrict__ bi) {
    int n = blockIdx.x * blockDim.x + threadIdx.x;
    if (n >= N3) return;
    float acc = g_bkqv[n];
    for (int d = 0; d < D_; d++)
        acc += bi[d] * (__bfloat162float(g_wkh[d * N3 + n]) +
                        __bfloat162float(g_wkl[d * N3 + n]));
    g_bfused[n] = acc;
}

// ---------------- MMA / ldmatrix / cp.async helpers ----------------
__device__ __forceinline__ void mma_bf16(float* d, const uint32_t* a, const uint32_t* b) {
    asm volatile("mma.sync.aligned.m16n8k16.row.col.f32.bf16.bf16.f32 "
                 "{%0,%1,%2,%3}, {%4,%5,%6,%7}, {%8,%9}, {%0,%1,%2,%3};"
                 : "+f"(d[0]), "+f"(d[1]), "+f"(d[2]), "+f"(d[3])
                 : "r"(a[0]), "r"(a[1]), "r"(a[2]), "r"(a[3]), "r"(b[0]), "r"(b[1]));
}

__device__ __forceinline__ void cp16(uint32_t dst, const void* src) {
    asm volatile("cp.async.cg.shared.global [%0], [%1], 16;" :: "r"(dst), "l"(src));
}
__device__ __forceinline__ void cp_commit() { asm volatile("cp.async.commit_group;"); }
template <int N> __device__ __forceinline__ void cp_wait() {
    asm volatile("cp.async.wait_group %0;" :: "n"(N));
}

// =======================================================================
// GEMM on pre-split hi/lo bf16 (proven R6 kernel)
// =======================================================================
#define GBM 128
#define GBN 128
#define GBK 32
#define SA_OFF 0
#define SB_OFF 16384
#define STAGE 32768
#define GEMM_SMEM (2 * STAGE)

__device__ __forceinline__ void g_ldmA(uint32_t* r, uint32_t sA, int m0, int kk, int hl, int lane) {
    int mrow  = m0 + (lane & 7) + ((lane >> 3) & 1) * 8;
    int chunk = ((kk >> 3) + (lane >> 4) + hl * 4) ^ (mrow & 7);
    uint32_t addr = sA + mrow * 128 + chunk * 16;
    asm volatile("ldmatrix.sync.aligned.m8n8.x4.shared.b16 {%0,%1,%2,%3}, [%4];"
                 : "=r"(r[0]), "=r"(r[1]), "=r"(r[2]), "=r"(r[3]) : "r"(addr));
}

__device__ __forceinline__ void g_ldmB(uint32_t* b0, uint32_t* b1, uint32_t sB,
                                       int kk, int nb, int hl, int lane) {
    int krow  = kk + (lane & 7) + ((lane >> 3) & 1) * 8;
    int nc    = nb + (lane >> 4) * 8;
    int chunk = (((nc >> 3) ^ (krow & 7)) + hl * 16);
    uint32_t addr = sB + krow * 512 + chunk * 16;
    uint32_t r0, r1, r2, r3;
    asm volatile("ldmatrix.sync.aligned.m8n8.x4.trans.shared.b16 {%0,%1,%2,%3}, [%4];"
                 : "=r"(r0), "=r"(r1), "=r"(r2), "=r"(r3) : "r"(addr));
    b0[0] = r0; b0[1] = r1; b1[0] = r2; b1[1] = r3;
}

// OM: 0 = fp32 C, 1 = hi/lo bf16 C
template <int OM>
__global__ void __launch_bounds__(256, 2)
gemm_pre(int M, int N, int K,
         const bf16* __restrict__ Ah, const bf16* __restrict__ Al,
         const bf16* __restrict__ Bh, const bf16* __restrict__ Bl,
         const float* __restrict__ bias, float* __restrict__ C,
         bf16* __restrict__ Ch, bf16* __restrict__ Cl) {
    extern __shared__ char sm[];
    const int tid = threadIdx.x, lane = tid & 31, wid = tid >> 5;
    const int bm = blockIdx.y, bn = blockIdx.x;
    const int warp_m = wid >> 2, warp_n = wid & 3;
    uint32_t sbase = (uint32_t)__cvta_generic_to_shared(sm);

    const int aRow = tid >> 1, aHL = tid & 1;
    const int bKr  = tid >> 3, bPiece = tid & 7;
    const int bHL  = bPiece >> 2, bQ = bPiece & 3;

    const bf16* Asrc = (aHL ? Al : Ah) + (size_t)(bm * GBM + aRow) * K;
    const bf16* Bsrc = (bHL ? Bl : Bh) + (size_t)bKr * N + bn * GBN;

    auto issue_stage = [&](int buf, int kt) {
        uint32_t sA = sbase + buf * STAGE + SA_OFF;
        uint32_t sB = sbase + buf * STAGE + SB_OFF;
        const bf16* a = Asrc + kt * GBK;
        #pragma unroll
        for (int j = 0; j < 4; j++) {
            int chunk = ((aHL * 4 + j) ^ (aRow & 7));
            cp16(sA + aRow * 128 + chunk * 16, a + j * 8);
        }
        const bf16* b = Bsrc + (size_t)kt * GBK * N;
        #pragma unroll
        for (int i = 0; i < 4; i++) {
            int c0 = bQ * 4 + i;
            int chunk = (c0 ^ (bKr & 7)) + bHL * 16;
            cp16(sB + bKr * 512 + chunk * 16, b + c0 * 8);
        }
        cp_commit();
    };

    float acc[4][4][4] = {};
    const int NT = K / GBK;

    issue_stage(0, 0);

    for (int kt = 0; kt < NT; kt++) {
        int cur = kt & 1;
        if (kt + 1 < NT) { issue_stage(cur ^ 1, kt + 1); cp_wait<1>(); }
        else             { cp_wait<0>(); }
        __syncthreads();

        uint32_t sA = sbase + cur * STAGE + SA_OFF;
        uint32_t sB = sbase + cur * STAGE + SB_OFF;

        #pragma unroll
        for (int kk = 0; kk < GBK; kk += 16) {
            uint32_t bh[4][2], bl[4][2];
            g_ldmB(bh[0], bh[1], sB, kk, warp_n * 32,      0, lane);
            g_ldmB(bh[2], bh[3], sB, kk, warp_n * 32 + 16, 0, lane);
            g_ldmB(bl[0], bl[1], sB, kk, warp_n * 32,      1, lane);
            g_ldmB(bl[2], bl[3], sB, kk, warp_n * 32 + 16, 1, lane);
            #pragma unroll
            for (int mt = 0; mt < 4; mt++) {
                uint32_t ah[4], al[4];
                g_ldmA(ah, sA, warp_m * 64 + mt * 16, kk, 0, lane);
                g_ldmA(al, sA, warp_m * 64 + mt * 16, kk, 1, lane);
                #pragma unroll
                for (int nt = 0; nt < 4; nt++) mma_bf16(acc[mt][nt], ah, bh[nt]);
                #pragma unroll
                for (int nt = 0; nt < 4; nt++) mma_bf16(acc[mt][nt], al, bh[nt]);
                #pragma unroll
                for (int nt = 0; nt < 4; nt++) mma_bf16(acc[mt][nt], ah, bl[nt]);
            }
        }
        __syncthreads();
    }

    #pragma unroll
    for (int mt = 0; mt < 4; mt++) {
        int r0 = bm * GBM + warp_m * 64 + mt * 16 + (lane >> 2);
        #pragma unroll
        for (int nt = 0; nt < 4; nt++) {
            int c = bn * GBN + warp_n * 32 + nt * 8 + (lane & 3) * 2;
            float2 b2 = *(const float2*)(bias + c);
            float v00 = acc[mt][nt][0] + b2.x, v01 = acc[mt][nt][1] + b2.y;
            float v10 = acc[mt][nt][2] + b2.x, v11 = acc[mt][nt][3] + b2.y;
            if (OM == 0) {
                *(float2*)(C + (size_t)r0 * N + c)       = make_float2(v00, v01);
                *(float2*)(C + (size_t)(r0 + 8) * N + c) = make_float2(v10, v11);
            } else {
                bf16 h0, l0, h1, l1;
                split1(v00, h0, l0); split1(v01, h1, l1);
                *(uint32_t*)(Ch + (size_t)r0 * N + c) =
                    (uint32_t)__bfloat16_as_ushort(h0) | ((uint32_t)__bfloat16_as_ushort(h1) << 16);
                *(uint32_t*)(Cl + (size_t)r0 * N + c) =
                    (uint32_t)__bfloat16_as_ushort(l0) | ((uint32_t)__bfloat16_as_ushort(l1) << 16);
                split1(v10, h0, l0); split1(v11, h1, l1);
                *(uint32_t*)(Ch + (size_t)(r0 + 8) * N + c) =
                    (uint32_t)__bfloat16_as_ushort(h0) | ((uint32_t)__bfloat16_as_ushort(h1) << 16);
                *(uint32_t*)(Cl + (size_t)(r0 + 8) * N + c) =
                    (uint32_t)__bfloat16_as_ushort(l0) | ((uint32_t)__bfloat16_as_ushort(l1) << 16);
            }
        }
    }
}

// =======================================================================
// Tensor-core flash attention, 128-row t-tiles, pre-split bf16 kqv
// smem: Kh 16K | Kl 16K | Qh 8K | Ql 8K | Vh 8K | Vl 8K = 64KB dynamic
// =======================================================================
#define ATT_K 16384
#define ATT_Q 8192
#define ATT_SMEM (2 * ATT_K + 4 * ATT_Q)

__device__ __forceinline__ void ldmKA(uint32_t* r, uint32_t base, int m0, int kk, int lane) {
    int mrow  = m0 + (lane & 7) + ((lane >> 3) & 1) * 8;
    int chunk = ((kk >> 3) + (lane >> 4)) ^ (mrow & 7);
    uint32_t addr = base + mrow * 128 + chunk * 16;
    asm volatile("ldmatrix.sync.aligned.m8n8.x4.shared.b16 {%0,%1,%2,%3}, [%4];"
                 : "=r"(r[0]), "=r"(r[1]), "=r"(r[2]), "=r"(r[3]) : "r"(addr));
}

__device__ __forceinline__ void ldmQB(uint32_t* t0, uint32_t* t1, uint32_t base,
                                      int n0, int kk, int lane) {
    int g     = lane >> 3;
    int nrow  = n0 + (lane & 7) + (g >> 1) * 8;
    int chunk = ((kk >> 3) + (g & 1)) ^ (nrow & 7);
    uint32_t addr = base + nrow * 128 + chunk * 16;
    uint32_t r0, r1, r2, r3;
    asm volatile("ldmatrix.sync.aligned.m8n8.x4.shared.b16 {%0,%1,%2,%3}, [%4];"
                 : "=r"(r0), "=r"(r1), "=r"(r2), "=r"(r3) : "r"(addr));
    t0[0] = r0; t0[1] = r1; t1[0] = r2; t1[1] = r3;
}

__device__ __forceinline__ void ldmVB(uint32_t* t0, uint32_t* t1, uint32_t base,
                                      int kk, int nb, int lane) {
    int krow  = kk + (lane & 7) + ((lane >> 3) & 1) * 8;
    int nc    = nb + (lane >> 4) * 8;
    int chunk = (nc >> 3) ^ (krow & 7);
    uint32_t addr = base + krow * 128 + chunk * 16;
    uint32_t r0, r1, r2, r3;
    asm volatile("ldmatrix.sync.aligned.m8n8.x4.trans.shared.b16 {%0,%1,%2,%3}, [%4];"
                 : "=r"(r0), "=r"(r1), "=r"(r2), "=r"(r3) : "r"(addr));
    t0[0] = r0; t0[1] = r1; t1[0] = r2; t1[1] = r3;
}

__device__ __forceinline__ void copy_half_row(const bf16* __restrict__ src,
                                              char* dst_base, int row, int half) {
    #pragma unroll
    for (int j = 0; j < 4; j++) {
        int chunk = (half * 4 + j) ^ (row & 7);
        *(uint4*)(dst_base + row * 128 + chunk * 16) = *(const uint4*)(src + j * 8);
    }
}

__global__ void __launch_bounds__(256)
attn_tc(const bf16* __restrict__ kqvh, const bf16* __restrict__ kqvl,
        bf16* __restrict__ outh, bf16* __restrict__ outl) {
    extern __shared__ __align__(16) char smem[];
    char* p_kh = smem;
    char* p_kl = smem + ATT_K;
    char* p_qh = smem + 2 * ATT_K;
    char* p_ql = p_qh + ATT_Q;
    char* p_vh = p_ql + ATT_Q;
    char* p_vl = p_vh + ATT_Q;

    const int tid = threadIdx.x, lane = tid & 31, w = tid >> 5;   // w: 0..7
    const int tchunk = blockIdx.x, h = blockIdx.y, b = blockIdx.z;
    const int tbase = tchunk * 128;

    uint32_t sb = (uint32_t)__cvta_generic_to_shared(smem);
    uint32_t s_kh = sb,             s_kl = sb + ATT_K;
    uint32_t s_qh = sb + 2 * ATT_K, s_ql = s_qh + ATT_Q;
    uint32_t s_vh = s_ql + ATT_Q,   s_vl = s_vh + ATT_Q;

    // ---- K tile: 128 rows ----
    {
        int row = tid >> 1, half = tid & 1;
        size_t off = (size_t)(b * T_ + tbase + row) * N3 + h * HD_ + half * 32;
        copy_half_row(kqvh + off, p_kh, row, half);
        copy_half_row(kqvl + off, p_kl, row, half);
    }
    __syncthreads();

    uint32_t kh[4][4], kl[4][4];
    #pragma unroll
    for (int ks = 0; ks < 4; ks++) {
        ldmKA(kh[ks], s_kh, w * 16, ks * 16, lane);
        ldmKA(kl[ks], s_kl, w * 16, ks * 16, lane);
    }

    float O[8][4];
    #pragma unroll
    for (int nt = 0; nt < 8; nt++)
        #pragma unroll
        for (int j = 0; j < 4; j++) O[nt][j] = 0.f;
    float m0 = NEG_INF, m1 = NEG_INF, l0 = 0.f, l1 = 0.f;

    const int qrow = tid >> 2, qq = tid & 3;   // 64-row Q/V loads: 2 chunks/thread/matrix
    const int cmax = 2 * tchunk + 1;

    for (int c = 0; c <= cmax; c++) {
        __syncthreads();
        {
            size_t off = (size_t)(b * T_ + c * 64 + qrow) * N3 + D_ + h * HD_;
            #pragma unroll
            for (int jj = 0; jj < 2; jj++) {
                int j = qq * 2 + jj;
                int chunk = j ^ (qrow & 7);
                int doff = qrow * 128 + chunk * 16;
                *(uint4*)(p_qh + doff) = *(const uint4*)(kqvh + off + j * 8);
                *(uint4*)(p_ql + doff) = *(const uint4*)(kqvl + off + j * 8);
                *(uint4*)(p_vh + doff) = *(const uint4*)(kqvh + off + D_ + j * 8);
                *(uint4*)(p_vl + doff) = *(const uint4*)(kqvl + off + D_ + j * 8);
            }
        }
        __syncthreads();

        // per-warp early-out: this warp's rows are all below the chunk
        if (c * 64 > tbase + w * 16 + 15) continue;

        float sa[8][4];
        #pragma unroll
        for (int nt = 0; nt < 8; nt++)
            #pragma unroll
            for (int j = 0; j < 4; j++) sa[nt][j] = 0.f;

        #pragma unroll
        for (int ks = 0; ks < 4; ks++) {
            uint32_t bq[8][2];
            #pragma unroll
            for (int np = 0; np < 4; np++)
                ldmQB(bq[2 * np], bq[2 * np + 1], s_qh, np * 16, ks * 16, lane);
            #pragma unroll
            for (int nt = 0; nt < 8; nt++) mma_bf16(sa[nt], kh[ks], bq[nt]);
            #pragma unroll
            for (int nt = 0; nt < 8; nt++) mma_bf16(sa[nt], kl[ks], bq[nt]);
            #pragma unroll
            for (int np = 0; np < 4; np++)
                ldmQB(bq[2 * np], bq[2 * np + 1], s_ql, np * 16, ks * 16, lane);
            #pragma unroll
            for (int nt = 0; nt < 8; nt++) mma_bf16(sa[nt], kh[ks], bq[nt]);
        }

        // causal mask (global index compare) where the chunk crosses the diagonal
        if (c * 64 + 63 > tbase + w * 16) {
            int rg = tbase + w * 16 + (lane >> 2);
            #pragma unroll
            for (int nt = 0; nt < 8; nt++) {
                int sg = c * 64 + nt * 8 + (lane & 3) * 2;
                if (sg + 0 > rg)     sa[nt][0] = NEG_INF;
                if (sg + 1 > rg)     sa[nt][1] = NEG_INF;
                if (sg + 0 > rg + 8) sa[nt][2] = NEG_INF;
                if (sg + 1 > rg + 8) sa[nt][3] = NEG_INF;
            }
        }

        float cm0 = NEG_INF, cm1 = NEG_INF;
        #pragma unroll
        for (int nt = 0; nt < 8; nt++) {
            cm0 = fmaxf(cm0, fmaxf(sa[nt][0], sa[nt][1]));
            cm1 = fmaxf(cm1, fmaxf(sa[nt][2], sa[nt][3]));
        }
        cm0 = fmaxf(cm0, __shfl_xor_sync(0xffffffffu, cm0, 1));
        cm0 = fmaxf(cm0, __shfl_xor_sync(0xffffffffu, cm0, 2));
        cm1 = fmaxf(cm1, __shfl_xor_sync(0xffffffffu, cm1, 1));
        cm1 = fmaxf(cm1, __shfl_xor_sync(0xffffffffu, cm1, 2));

        float mn0 = fmaxf(m0, cm0), mn1 = fmaxf(m1, cm1);
        float al0 = __expf(m0 - mn0), al1 = __expf(m1 - mn1);
        m0 = mn0; m1 = mn1;
        l0 *= al0; l1 *= al1;
        #pragma unroll
        for (int nt = 0; nt < 8; nt++) {
            O[nt][0] *= al0; O[nt][1] *= al0;
            O[nt][2] *= al1; O[nt][3] *= al1;
        }

        #pragma unroll
        for (int nt = 0; nt < 8; nt++) {
            sa[nt][0] = __expf(sa[nt][0] - m0);
            sa[nt][1] = __expf(sa[nt][1] - m0);
            sa[nt][2] = __expf(sa[nt][2] - m1);
            sa[nt][3] = __expf(sa[nt][3] - m1);
            l0 += sa[nt][0] + sa[nt][1];
            l1 += sa[nt][2] + sa[nt][3];
        }

        #pragma unroll
        for (int ks = 0; ks < 4; ks++) {
            uint32_t ah[4], al[4];
            #pragma unroll
            for (int q = 0; q < 2; q++) {
                float p0 = sa[2 * ks][2 * q],     p1 = sa[2 * ks][2 * q + 1];
                float p2 = sa[2 * ks + 1][2 * q], p3 = sa[2 * ks + 1][2 * q + 1];
                bf16 h0, e0, h1, e1, h2, e2, h3, e3;
                split1(p0, h0, e0); split1(p1, h1, e1);
                split1(p2, h2, e2); split1(p3, h3, e3);
                ah[q]     = (uint32_t)__bfloat16_as_ushort(h0) | ((uint32_t)__bfloat16_as_ushort(h1) << 16);
                ah[q + 2] = (uint32_t)__bfloat16_as_ushort(h2) | ((uint32_t)__bfloat16_as_ushort(h3) << 16);
                al[q]     = (uint32_t)__bfloat16_as_ushort(e0) | ((uint32_t)__bfloat16_as_ushort(e1) << 16);
                al[q + 2] = (uint32_t)__bfloat16_as_ushort(e2) | ((uint32_t)__bfloat16_as_ushort(e3) << 16);
            }
            uint32_t bv[8][2];
            #pragma unroll
            for (int np = 0; np < 4; np++)
                ldmVB(bv[2 * np], bv[2 * np + 1], s_vh, ks * 16, np * 16, lane);
            #pragma unroll
            for (int nt = 0; nt < 8; nt++) mma_bf16(O[nt], ah, bv[nt]);
            #pragma unroll
            for (int nt = 0; nt < 8; nt++) mma_bf16(O[nt], al, bv[nt]);
            #pragma unroll
            for (int np = 0; np < 4; np++)
                ldmVB(bv[2 * np], bv[2 * np + 1], s_vl, ks * 16, np * 16, lane);
            #pragma unroll
            for (int nt = 0; nt < 8; nt++) mma_bf16(O[nt], ah, bv[nt]);
        }
    }

    l0 += __shfl_xor_sync(0xffffffffu, l0, 1);
    l0 += __shfl_xor_sync(0xffffffffu, l0, 2);
    l1 += __shfl_xor_sync(0xffffffffu, l1, 1);
    l1 += __shfl_xor_sync(0xffffffffu, l1, 2);
    float inv0 = 1.f / l0, inv1 = 1.f / l1;

    int r0 = tbase + w * 16 + (lane >> 2);
    #pragma unroll
    for (int nt = 0; nt < 8; nt++) {
        int col = h * HD_ + nt * 8 + (lane & 3) * 2;
        float v00 = O[nt][0] * inv0, v01 = O[nt][1] * inv0;
        float v10 = O[nt][2] * inv1, v11 = O[nt][3] * inv1;
        bf16 h0, e0, h1, e1;
        split1(v00, h0, e0); split1(v01, h1, e1);
        *(uint32_t*)(outh + (size_t)(b * T_ + r0) * D_ + col) =
            (uint32_t)__bfloat16_as_ushort(h0) | ((uint32_t)__bfloat16_as_ushort(h1) << 16);
        *(uint32_t*)(outl + (size_t)(b * T_ + r0) * D_ + col) =
            (uint32_t)__bfloat16_as_ushort(e0) | ((uint32_t)__bfloat16_as_ushort(e1) << 16);
        split1(v10, h0, e0); split1(v11, h1, e1);
        *(uint32_t*)(outh + (size_t)(b * T_ + r0 + 8) * D_ + col) =
            (uint32_t)__bfloat16_as_ushort(h0) | ((uint32_t)__bfloat16_as_ushort(h1) << 16);
        *(uint32_t*)(outl + (size_t)(b * T_ + r0 + 8) * D_ + col) =
            (uint32_t)__bfloat16_as_ushort(e0) | ((uint32_t)__bfloat16_as_ushort(e1) << 16);
    }
}

// ---------------- launch ----------------
extern "C" void kernel_launch(void* const* d_in, const int* in_sizes, int n_in,
                              void* d_out, int out_size) {
    const float* x  = (const float*)d_in[0];
    const float* Wi = (const float*)d_in[1];
    const float* bi = (const float*)d_in[2];
    const float* Wk = (const float*)d_in[3];
    const float* bk = (const float*)d_in[4];
    const float* Wq = (const float*)d_in[5];
    const float* bq = (const float*)d_in[6];
    const float* Wv = (const float*)d_in[7];
    const float* bv = (const float*)d_in[8];
    const float* Wo = (const float*)d_in[9];
    const float* bo = (const float*)d_in[10];
    float* out = (float*)d_out;

    bf16 *p_xh, *p_xl, *p_kqvh, *p_kqvl, *p_ah, *p_al;
    bf16 *p_wih, *p_wil, *p_wkh, *p_wkl, *p_wph, *p_wpl, *p_woh, *p_wol;
    float *p_bfused, *p_zero;
    cudaGetSymbolAddress((void**)&p_xh, g_xh);     cudaGetSymbolAddress((void**)&p_xl, g_xl);
    cudaGetSymbolAddress((void**)&p_kqvh, g_kqvh); cudaGetSymbolAddress((void**)&p_kqvl, g_kqvl);
    cudaGetSymbolAddress((void**)&p_ah, g_ah);     cudaGetSymbolAddress((void**)&p_al, g_al);
    cudaGetSymbolAddress((void**)&p_wih, g_wih);   cudaGetSymbolAddress((void**)&p_wil, g_wil);
    cudaGetSymbolAddress((void**)&p_wkh, g_wkh);   cudaGetSymbolAddress((void**)&p_wkl, g_wkl);
    cudaGetSymbolAddress((void**)&p_wph, g_wph);   cudaGetSymbolAddress((void**)&p_wpl, g_wpl);
    cudaGetSymbolAddress((void**)&p_woh, g_woh);   cudaGetSymbolAddress((void**)&p_wol, g_wol);
    cudaGetSymbolAddress((void**)&p_bfused, g_bfused);
    cudaGetSymbolAddress((void**)&p_zero, g_zero);

    static bool attr_set = false;
    if (!attr_set) {
        cudaFuncSetAttribute(gemm_pre<0>, cudaFuncAttributeMaxDynamicSharedMemorySize, GEMM_SMEM);
        cudaFuncSetAttribute(gemm_pre<1>, cudaFuncAttributeMaxDynamicSharedMemorySize, GEMM_SMEM);
        cudaFuncSetAttribute(attn_tc,     cudaFuncAttributeMaxDynamicSharedMemorySize, ATT_SMEM);
        attr_set = true;
    }

    // splits / repack
    split_kernel<<<(M_ * D_ / 4 + 255) / 256, 256>>>(x,  p_xh,  p_xl,  M_ * D_);
    split_kernel<<<(D_ * D_ / 4 + 255) / 256, 256>>>(Wi, p_wih, p_wil, D_ * D_);
    split_kernel<<<(D_ * D_ / 4 + 255) / 256, 256>>>(Wo, p_woh, p_wol, D_ * D_);
    repack_split_kernel<<<(3 * H_ * D_ * HD_ + 255) / 256, 256>>>(Wk, Wq, Wv, bk, bq, bv);
    bias_fuse_kernel<<<(N3 + 255) / 256, 256>>>(bi);

    {   // W' = Wi @ Wkqv  -> hi/lo   [1024 x 3072]
        dim3 grid(N3 / GBN, D_ / GBM);
        gemm_pre<1><<<grid, 256, GEMM_SMEM>>>(D_, N3, D_, p_wih, p_wil, p_wkh, p_wkl,
                                              p_zero, nullptr, p_wph, p_wpl);
    }
    {   // kqv = x @ W' + b'  -> hi/lo   [16384 x 3072]
        dim3 grid(N3 / GBN, M_ / GBM);
        gemm_pre<1><<<grid, 256, GEMM_SMEM>>>(M_, N3, D_, p_xh, p_xl, p_wph, p_wpl,
                                              p_bfused, nullptr, p_kqvh, p_kqvl);
    }
    {   // attention -> hi/lo  (128-row t-tiles)
        dim3 grid(T_ / 128, H_, B_);
        attn_tc<<<grid, 256, ATT_SMEM>>>(p_kqvh, p_kqvl, p_ah, p_al);
    }
    {   // out = attn @ Wo + bo -> fp32
        dim3 grid(D_ / GBN, M_ / GBM);
        gemm_pre<0><<<grid, 256, GEMM_SMEM>>>(M_, D_, D_, p_ah, p_al, p_woh, p_wol,
                                              bo, out, nullptr, nullptr);
    }
}